// round 9
// baseline (speedup 1.0000x reference)
#include <cuda_runtime.h>
#include <cstdint>

#define BB 8
#define TT 2048
#define DD 256
#define HH 4
#define HDIM 64
#define NT (BB*TT)           // 16384 rows
#define NROWS (BB*HH*TT)     // 65536 attention score rows
#define NEGV (-1e9f)
#define EPSV 1e-5f
#define CAND_CAP 512

// ---------------- device scratch (module-load allocated) --------------------
__device__ float g_Q[BB*HH*TT*HDIM];
__device__ float g_K[BB*HH*TT*HDIM];
__device__ float g_V[BB*HH*TT*HDIM];
__device__ float g_S[(size_t)BB*HH*TT*TT];   // 512 MiB score scratch
__device__ float g_attn[NT*DD];
__device__ unsigned char g_pad[NT];

// ---------------- packed fp32x2 helpers -------------------------------------
union F2U { unsigned long long u; float2 f; };

__device__ __forceinline__ void ffma2(unsigned long long& acc,
                                      unsigned long long a, unsigned long long b) {
    asm("fma.rn.f32x2 %0, %1, %2, %0;" : "+l"(acc) : "l"(a), "l"(b));
}
__device__ __forceinline__ float hsum2(unsigned long long u) {
    F2U t; t.u = u; return t.f.x + t.f.y;
}

#define F_SWZ(r) ((((r) >> 2) ^ ((r) >> 5)) & 7)

// ---------------- mask dtype detection + expansion --------------------------
__global__ void mask_prep_kernel(const void* __restrict__ maskraw) {
    __shared__ int cntOff, cnt3F, mode;
    const unsigned char* b = (const unsigned char*)maskraw;
    int tid = threadIdx.x;
    if (tid == 0) { cntOff = 0; cnt3F = 0; }
    __syncthreads();
    int lo = 0, l3 = 0;
    for (int i = tid; i < NT; i += blockDim.x) {
        unsigned char v = b[i];
        if ((i & 3) != 0 && v != 0) lo++;
        if ((i & 3) == 3 && v == 0x3F) l3++;
    }
    atomicAdd(&cntOff, lo);
    atomicAdd(&cnt3F, l3);
    __syncthreads();
    if (tid == 0) {
        if (cnt3F > 0) mode = 2;            // float32
        else if (cntOff > 0) mode = 0;      // uint8 / bool
        else mode = 1;                      // int32
    }
    __syncthreads();
    int m = mode;
    for (int i = tid; i < NT; i += blockDim.x) {
        unsigned char p;
        if (m == 0)      p = (b[i] != 0);
        else if (m == 1) p = (((const int*)maskraw)[i] != 0);
        else             p = (((const float*)maskraw)[i] != 0.0f);
        g_pad[i] = p;
    }
}

// ---------------- QKV projection (known-good) --------------------------------
__global__ __launch_bounds__(256)
void qkv_proj_kernel(const float* __restrict__ x,
                     const float* __restrict__ Wq,
                     const float* __restrict__ Wk,
                     const float* __restrict__ Wv) {
    __shared__ float4 Xs4[512];   // 64 rows x 8 chunks
    __shared__ float4 Ws4[512];
    const float* W = (blockIdx.z == 0) ? Wq : (blockIdx.z == 1 ? Wk : Wv);
    float* O       = (blockIdx.z == 0) ? g_Q : (blockIdx.z == 1 ? g_K : g_V);
    int n0 = blockIdx.x * 64;
    int h  = blockIdx.y;
    int j0 = h * 64;
    int tid = threadIdx.x;
    int tx = tid & 15, ty = tid >> 4;

    int f0 = tid * 2;
    int lr = f0 >> 3, lc = f0 & 7;
    int wxor = ((lr >> 2) & 7) ^ ((lr & 3) << 1);

    const float4* xg = (const float4*)&x[(size_t)(n0 + lr) * DD];
    const float4* wg = (const float4*)&W[(size_t)(j0 + lr) * DD];
    float4 px0 = xg[lc], px1 = xg[lc + 1];
    float4 pw0 = wg[lc], pw1 = wg[lc + 1];

    unsigned long long acc[4][4] = {};

    for (int kk = 0; kk < DD; kk += 32) {
        __syncthreads();
        Xs4[lr * 8 + lc]              = px0;
        Xs4[lr * 8 + lc + 1]          = px1;
        Ws4[lr * 8 + (lc ^ wxor)]     = pw0;
        Ws4[lr * 8 + ((lc + 1) ^ wxor)] = pw1;
        if (kk + 32 < DD) {
            int o = (kk + 32) >> 2;
            px0 = xg[o + lc]; px1 = xg[o + lc + 1];
            pw0 = wg[o + lc]; pw1 = wg[o + lc + 1];
        }
        __syncthreads();
        #pragma unroll
        for (int c = 0; c < 8; c++) {
            ulonglong2 xs[4], ws[4];
            #pragma unroll
            for (int i = 0; i < 4; i++)
                xs[i] = *(const ulonglong2*)&Xs4[(ty * 4 + i) * 8 + c];
            #pragma unroll
            for (int j = 0; j < 4; j++)
                ws[j] = *(const ulonglong2*)&Ws4[(tx * 4 + j) * 8 +
                                                 (c ^ (tx & 7) ^ (j << 1))];
            #pragma unroll
            for (int i = 0; i < 4; i++)
                #pragma unroll
                for (int j = 0; j < 4; j++) {
                    ffma2(acc[i][j], xs[i].x, ws[j].x);
                    ffma2(acc[i][j], xs[i].y, ws[j].y);
                }
        }
    }
    #pragma unroll
    for (int i = 0; i < 4; i++) {
        int n = n0 + ty * 4 + i;
        int bi = n >> 11, t = n & (TT - 1);
        float* orow = O + (((size_t)bi * HH + h) * TT + t) * HDIM + tx * 4;
        float4 v = make_float4(hsum2(acc[i][0]), hsum2(acc[i][1]),
                               hsum2(acc[i][2]), hsum2(acc[i][3]));
        *(float4*)orow = v;
    }
}

// ---------------- score GEMM: S = (Q/8) K^T, 128q x 128k tiles, 512 thr -----
// 8q x 4k per thread; Q operand reads warp-uniform broadcast (ty const/warp),
// K reads conflict-free via F_SWZ.
#define SMEM_SCORE_BYTES (2 * 128 * 16 * sizeof(float4))   // 64 KB

__global__ __launch_bounds__(512, 2)
void score_kernel() {
    extern __shared__ float4 sm4[];
    float4* sQ4 = sm4;          // 128 rows x 16 chunks
    float4* sK4 = sm4 + 2048;
    int tid = threadIdx.x;
    int kt = blockIdx.x & 15;
    int qt = blockIdx.x >> 4;
    int h = blockIdx.y, b = blockIdx.z;

    const float4* Qg = (const float4*)(g_Q + ((size_t)(b * HH + h) * TT + qt * 128) * HDIM);
    const float4* Kg = (const float4*)(g_K + ((size_t)(b * HH + h) * TT + kt * 128) * HDIM);

    #pragma unroll
    for (int s = 0; s < 4; s++) {
        int idx = s * 512 + tid;
        int r = idx >> 4, c = idx & 15;
        float4 v = Qg[idx];
        v.x *= 0.125f; v.y *= 0.125f; v.z *= 0.125f; v.w *= 0.125f;
        sQ4[r * 16 + (c ^ F_SWZ(r))] = v;
        sK4[r * 16 + (c ^ F_SWZ(r))] = Kg[idx];
    }
    __syncthreads();

    int tx = tid & 31;          // 4 keys each
    int ty = tid >> 5;          // 8 query rows each (uniform per warp)
    unsigned long long acc[8][4] = {};

    #pragma unroll 4
    for (int c = 0; c < 16; c++) {
        ulonglong2 qf[8], kf[4];
        #pragma unroll
        for (int i = 0; i < 8; i++) {
            int r = ty * 8 + i;
            qf[i] = *(const ulonglong2*)&sQ4[r * 16 + (c ^ F_SWZ(r))];
        }
        #pragma unroll
        for (int j = 0; j < 4; j++) {
            int r = tx * 4 + j;
            kf[j] = *(const ulonglong2*)&sK4[r * 16 + (c ^ F_SWZ(r))];
        }
        #pragma unroll
        for (int i = 0; i < 8; i++)
            #pragma unroll
            for (int j = 0; j < 4; j++) {
                ffma2(acc[i][j], qf[i].x, kf[j].x);
                ffma2(acc[i][j], qf[i].y, kf[j].y);
            }
    }

    float* Sout = g_S + ((size_t)(b * HH + h) * TT + qt * 128 + ty * 8) * TT
                + kt * 128 + tx * 4;
    #pragma unroll
    for (int i = 0; i < 8; i++) {
        float4 v = make_float4(hsum2(acc[i][0]), hsum2(acc[i][1]),
                               hsum2(acc[i][2]), hsum2(acc[i][3]));
        *(float4*)&Sout[(size_t)i * TT] = v;
    }
}

// ---------------- sparsemax + sparse AV: 1 warp per score row ---------------
// Candidate compaction: only z > zmax-1 can be in the support (tau >= zmax-1).
__global__ __launch_bounds__(256)
void spmax_av_kernel() {
    __shared__ float sVal[8 * CAND_CAP];           // 16 KB
    __shared__ unsigned short sKey[8 * CAND_CAP];  // 8 KB
    int wid = threadIdx.x >> 5, lane = threadIdx.x & 31;
    int rid = blockIdx.x * 8 + wid;               // [0, NROWS)
    int b = rid >> 13, h = (rid >> 11) & 3, q = rid & 2047;

    const float4* Srow = (const float4*)(g_S + (size_t)rid * TT);
    const uchar4* pad4 = (const uchar4*)(g_pad + b * TT);

    // load row: z[it*4+j] holds key it*128 + lane*4 + j
    float z[64];
    float zmax = -3e38f;
    #pragma unroll
    for (int it = 0; it < 16; it++) {
        float4 sv = Srow[it * 32 + lane];
        uchar4 p = pad4[it * 32 + lane];
        float z0 = p.x ? NEGV : sv.x;
        float z1 = p.y ? NEGV : sv.y;
        float z2 = p.z ? NEGV : sv.z;
        float z3 = p.w ? NEGV : sv.w;
        z[it * 4 + 0] = z0; z[it * 4 + 1] = z1;
        z[it * 4 + 2] = z2; z[it * 4 + 3] = z3;
        zmax = fmaxf(fmaxf(fmaxf(zmax, z0), fmaxf(z1, z2)), z3);
    }
    #pragma unroll
    for (int o = 16; o; o >>= 1) zmax = fmaxf(zmax, __shfl_xor_sync(0xffffffffu, zmax, o));

    // ---- candidate compaction ----
    float lim = zmax - 1.0f;
    int base = wid * CAND_CAP;
    unsigned cnt = 0;
    #pragma unroll
    for (int i = 0; i < 64; i++) {
        bool cand = z[i] > lim;
        unsigned m = __ballot_sync(0xffffffffu, cand);
        if (cand) {
            int pos = cnt + __popc(m & ((1u << lane) - 1u));
            if (pos < CAND_CAP) {
                sVal[base + pos] = z[i];
                sKey[base + pos] = (unsigned short)(((i >> 2) << 7) + (lane << 2) + (i & 3));
            }
        }
        cnt += __popc(m);
    }
    __syncwarp();

    const float* Vb = g_V + ((size_t)(b * HH + h) * TT) * HDIM;
    float2 acc = make_float2(0.f, 0.f);

    if (cnt <= CAND_CAP) {
        // ---- Newton over compact list ----
        float tau = lim;
        int n = (int)cnt;
        for (int it = 0; it < 32; it++) {
            float s = 0.f, c = 0.f;
            for (int j = lane; j < n; j += 32) {
                float v = sVal[base + j];
                if (v > tau) { s += v; c += 1.0f; }
            }
            #pragma unroll
            for (int o = 16; o; o >>= 1) {
                s += __shfl_xor_sync(0xffffffffu, s, o);
                c += __shfl_xor_sync(0xffffffffu, c, o);
            }
            float nt = (s - 1.0f) / c;
            if (nt == tau) break;
            tau = nt;
        }
        // ---- AV over compact list (uniform broadcast) ----
        for (int j = 0; j < n; j++) {
            float v = sVal[base + j];
            float w = v - tau;
            if (w > 0.f) {
                int k = sKey[base + j];
                float2 vv = *(const float2*)&Vb[(size_t)k * HDIM + lane * 2];
                acc.x += w * vv.x;
                acc.y += w * vv.y;
            }
        }
    } else {
        // ---- fallback: full-register Newton + ballot-pop AV (exact) ----
        float tau = lim;
        for (int it = 0; it < 32; it++) {
            float s = 0.f, c = 0.f;
            #pragma unroll
            for (int i = 0; i < 64; i++) {
                if (z[i] > tau) { s += z[i]; c += 1.0f; }
            }
            #pragma unroll
            for (int o = 16; o; o >>= 1) {
                s += __shfl_xor_sync(0xffffffffu, s, o);
                c += __shfl_xor_sync(0xffffffffu, c, o);
            }
            float nt = (s - 1.0f) / c;
            if (nt == tau) break;
            tau = nt;
        }
        #pragma unroll
        for (int g = 0; g < 16; g++) {
            #pragma unroll
            for (int j = 0; j < 4; j++) {
                float zz = z[g * 4 + j];
                unsigned m = __ballot_sync(0xffffffffu, zz > tau);
                while (m) {
                    int src = __ffs(m) - 1;
                    m &= m - 1;
                    float w = __shfl_sync(0xffffffffu, zz, src) - tau;
                    int k = g * 128 + src * 4 + j;
                    float2 v = *(const float2*)&Vb[(size_t)k * HDIM + lane * 2];
                    acc.x += w * v.x;
                    acc.y += w * v.y;
                }
            }
        }
    }
    *(float2*)&g_attn[((size_t)b * TT + q) * DD + h * HDIM + lane * 2] = acc;
}

// ---------------- out-proj + residual + LayerNorm (known-good) --------------
__global__ __launch_bounds__(256)
void outproj_ln_kernel(const float* __restrict__ x,
                       const float* __restrict__ Wo,
                       const float* __restrict__ gamma,
                       const float* __restrict__ beta,
                       float* __restrict__ out) {
    __shared__ float sA[16][DD];
    __shared__ float sY[16][DD + 1];
    __shared__ float sMu[16], sRs[16];
    int n0 = blockIdx.x * 16;
    int tid = threadIdx.x;              // output column j

    for (int i = tid; i < 16 * 64; i += 256) {
        int r = i >> 6, c4 = (i & 63) * 4;
        *(float4*)&sA[r][c4] = *(const float4*)&g_attn[((size_t)n0 + r) * DD + c4];
    }
    __syncthreads();

    unsigned long long acc2[16] = {};
    const ulonglong2* wrow = (const ulonglong2*)(Wo + (size_t)tid * DD);
    #pragma unroll 4
    for (int c = 0; c < 64; c++) {
        ulonglong2 w = wrow[c];
        #pragma unroll
        for (int r = 0; r < 16; r++) {
            ulonglong2 a = *(const ulonglong2*)&sA[r][c * 4];
            ffma2(acc2[r], w.x, a.x);
            ffma2(acc2[r], w.y, a.y);
        }
    }
    #pragma unroll
    for (int r = 0; r < 16; r++)
        sY[r][tid] = hsum2(acc2[r]) + x[((size_t)n0 + r) * DD + tid];
    __syncthreads();

    int wid = tid >> 5, lane = tid & 31;
    for (int rr = 0; rr < 2; rr++) {
        int r = wid * 2 + rr;
        float s = 0.f, s2 = 0.f;
        #pragma unroll
        for (int i = 0; i < 8; i++) {
            float v = sY[r][lane * 8 + i];
            s += v; s2 += v * v;
        }
        #pragma unroll
        for (int o = 16; o; o >>= 1) {
            s  += __shfl_xor_sync(0xffffffffu, s, o);
            s2 += __shfl_xor_sync(0xffffffffu, s2, o);
        }
        if (lane == 0) {
            float mu = s * (1.0f / DD);
            sMu[r] = mu;
            sRs[r] = rsqrtf(s2 * (1.0f / DD) - mu * mu + EPSV);
        }
    }
    __syncthreads();
    float g = gamma[tid], bt = beta[tid];
    #pragma unroll
    for (int r = 0; r < 16; r++)
        out[((size_t)n0 + r) * DD + tid] = (sY[r][tid] - sMu[r]) * sRs[r] * g + bt;
}

// ---------------- launch ----------------------------------------------------
extern "C" void kernel_launch(void* const* d_in, const int* in_sizes, int n_in,
                              void* d_out, int out_size) {
    const float* x     = (const float*)d_in[0];
    const void*  mask  = d_in[1];
    const float* Wq    = (const float*)d_in[2];
    const float* Wk    = (const float*)d_in[3];
    const float* Wv    = (const float*)d_in[4];
    const float* Wo    = (const float*)d_in[5];
    const float* gamma = (const float*)d_in[6];
    const float* beta  = (const float*)d_in[7];
    float* out = (float*)d_out;

    cudaFuncSetAttribute(score_kernel, cudaFuncAttributeMaxDynamicSharedMemorySize,
                         SMEM_SCORE_BYTES);

    mask_prep_kernel<<<1, 256>>>(mask);
    qkv_proj_kernel<<<dim3(NT / 64, HH, 3), 256>>>(x, Wq, Wk, Wv);
    score_kernel<<<dim3(256, HH, BB), 512, SMEM_SCORE_BYTES>>>();
    spmax_av_kernel<<<NROWS / 8, 256>>>();
    outproj_ln_kernel<<<NT / 16, 256>>>(x, Wo, gamma, beta, out);
}

// round 10
// speedup vs baseline: 2.6468x; 2.6468x over previous
#include <cuda_runtime.h>
#include <cstdint>

#define BB 8
#define TT 2048
#define DD 256
#define HH 4
#define HDIM 64
#define NT (BB*TT)           // 16384 rows
#define NROWS (BB*HH*TT)     // 65536 attention score rows
#define NEGV (-1e9f)
#define EPSV 1e-5f
#define CAND_CAP 512

// ---------------- device scratch (module-load allocated) --------------------
__device__ float g_Q[BB*HH*TT*HDIM];
__device__ float g_K[BB*HH*TT*HDIM];
__device__ float g_V[BB*HH*TT*HDIM];
__device__ float g_S[(size_t)BB*HH*TT*TT];   // 512 MiB score scratch
__device__ float g_attn[NT*DD];
__device__ unsigned char g_pad[NT];

// ---------------- packed fp32x2 helpers -------------------------------------
union F2U { unsigned long long u; float2 f; };

__device__ __forceinline__ void ffma2(unsigned long long& acc,
                                      unsigned long long a, unsigned long long b) {
    asm("fma.rn.f32x2 %0, %1, %2, %0;" : "+l"(acc) : "l"(a), "l"(b));
}
__device__ __forceinline__ float hsum2(unsigned long long u) {
    F2U t; t.u = u; return t.f.x + t.f.y;
}

// ---------------- mask dtype detection + expansion --------------------------
__global__ void mask_prep_kernel(const void* __restrict__ maskraw) {
    __shared__ int cntOff, cnt3F, mode;
    const unsigned char* b = (const unsigned char*)maskraw;
    int tid = threadIdx.x;
    if (tid == 0) { cntOff = 0; cnt3F = 0; }
    __syncthreads();
    int lo = 0, l3 = 0;
    for (int i = tid; i < NT; i += blockDim.x) {
        unsigned char v = b[i];
        if ((i & 3) != 0 && v != 0) lo++;
        if ((i & 3) == 3 && v == 0x3F) l3++;
    }
    atomicAdd(&cntOff, lo);
    atomicAdd(&cnt3F, l3);
    __syncthreads();
    if (tid == 0) {
        if (cnt3F > 0) mode = 2;            // float32
        else if (cntOff > 0) mode = 0;      // uint8 / bool
        else mode = 1;                      // int32
    }
    __syncthreads();
    int m = mode;
    for (int i = tid; i < NT; i += blockDim.x) {
        unsigned char p;
        if (m == 0)      p = (b[i] != 0);
        else if (m == 1) p = (((const int*)maskraw)[i] != 0);
        else             p = (((const float*)maskraw)[i] != 0.0f);
        g_pad[i] = p;
    }
}

// ---------------- QKV projection (known-good) --------------------------------
__global__ __launch_bounds__(256)
void qkv_proj_kernel(const float* __restrict__ x,
                     const float* __restrict__ Wq,
                     const float* __restrict__ Wk,
                     const float* __restrict__ Wv) {
    __shared__ float4 Xs4[512];   // 64 rows x 8 chunks
    __shared__ float4 Ws4[512];
    const float* W = (blockIdx.z == 0) ? Wq : (blockIdx.z == 1 ? Wk : Wv);
    float* O       = (blockIdx.z == 0) ? g_Q : (blockIdx.z == 1 ? g_K : g_V);
    int n0 = blockIdx.x * 64;
    int h  = blockIdx.y;
    int j0 = h * 64;
    int tid = threadIdx.x;
    int tx = tid & 15, ty = tid >> 4;

    int f0 = tid * 2;
    int lr = f0 >> 3, lc = f0 & 7;
    int wxor = ((lr >> 2) & 7) ^ ((lr & 3) << 1);

    const float4* xg = (const float4*)&x[(size_t)(n0 + lr) * DD];
    const float4* wg = (const float4*)&W[(size_t)(j0 + lr) * DD];
    float4 px0 = xg[lc], px1 = xg[lc + 1];
    float4 pw0 = wg[lc], pw1 = wg[lc + 1];

    unsigned long long acc[4][4] = {};

    for (int kk = 0; kk < DD; kk += 32) {
        __syncthreads();
        Xs4[lr * 8 + lc]              = px0;
        Xs4[lr * 8 + lc + 1]          = px1;
        Ws4[lr * 8 + (lc ^ wxor)]     = pw0;
        Ws4[lr * 8 + ((lc + 1) ^ wxor)] = pw1;
        if (kk + 32 < DD) {
            int o = (kk + 32) >> 2;
            px0 = xg[o + lc]; px1 = xg[o + lc + 1];
            pw0 = wg[o + lc]; pw1 = wg[o + lc + 1];
        }
        __syncthreads();
        #pragma unroll
        for (int c = 0; c < 8; c++) {
            ulonglong2 xs[4], ws[4];
            #pragma unroll
            for (int i = 0; i < 4; i++)
                xs[i] = *(const ulonglong2*)&Xs4[(ty * 4 + i) * 8 + c];
            #pragma unroll
            for (int j = 0; j < 4; j++)
                ws[j] = *(const ulonglong2*)&Ws4[(tx * 4 + j) * 8 +
                                                 (c ^ (tx & 7) ^ (j << 1))];
            #pragma unroll
            for (int i = 0; i < 4; i++)
                #pragma unroll
                for (int j = 0; j < 4; j++) {
                    ffma2(acc[i][j], xs[i].x, ws[j].x);
                    ffma2(acc[i][j], xs[i].y, ws[j].y);
                }
        }
    }
    #pragma unroll
    for (int i = 0; i < 4; i++) {
        int n = n0 + ty * 4 + i;
        int bi = n >> 11, t = n & (TT - 1);
        float* orow = O + (((size_t)bi * HH + h) * TT + t) * HDIM + tx * 4;
        float4 v = make_float4(hsum2(acc[i][0]), hsum2(acc[i][1]),
                               hsum2(acc[i][2]), hsum2(acc[i][3]));
        *(float4*)orow = v;
    }
}

// ---------------- score GEMM: S = (Q/8) K^T, 128q x 64k tiles (round-8) -----
__global__ __launch_bounds__(256, 2)
void score_kernel() {
    __shared__ float4 sQ4[128 * 16];   // 32 KB
    __shared__ float4 sK4[64 * 16];    // 16 KB
    int tid = threadIdx.x;
    int kt = blockIdx.x & 31;          // 32 tiles of 64 keys
    int qt = blockIdx.x >> 5;          // 16 tiles of 128 queries
    int h = blockIdx.y, b = blockIdx.z;

    const float4* Qg = (const float4*)(g_Q + ((size_t)(b * HH + h) * TT + qt * 128) * HDIM);
    const float4* Kg = (const float4*)(g_K + ((size_t)(b * HH + h) * TT + kt * 64) * HDIM);

    #pragma unroll
    for (int s = 0; s < 8; s++) {
        int idx = s * 256 + tid;
        int r = idx >> 4, c = idx & 15;
        float4 v = Qg[idx];
        v.x *= 0.125f; v.y *= 0.125f; v.z *= 0.125f; v.w *= 0.125f;
        sQ4[r * 16 + (c ^ ((r >> 2) & 7))] = v;
    }
    #pragma unroll
    for (int s = 0; s < 4; s++) {
        int idx = s * 256 + tid;
        int r = idx >> 4, c = idx & 15;
        sK4[r * 16 + (c ^ ((r >> 2) & 7))] = Kg[idx];
    }
    __syncthreads();

    int tx = tid & 15, ty = tid >> 4;   // tx -> 4 keys, ty -> 8 queries
    unsigned long long acc[8][4] = {};
    #pragma unroll 4
    for (int c = 0; c < 16; c++) {
        ulonglong2 qf[8], kf[4];
        #pragma unroll
        for (int i = 0; i < 8; i++) {
            int r = ty * 8 + i;
            qf[i] = *(const ulonglong2*)&sQ4[r * 16 + (c ^ ((r >> 2) & 7))];
        }
        #pragma unroll
        for (int j = 0; j < 4; j++) {
            int r = tx * 4 + j;
            kf[j] = *(const ulonglong2*)&sK4[r * 16 + (c ^ ((r >> 2) & 7))];
        }
        #pragma unroll
        for (int i = 0; i < 8; i++)
            #pragma unroll
            for (int j = 0; j < 4; j++) {
                ffma2(acc[i][j], qf[i].x, kf[j].x);
                ffma2(acc[i][j], qf[i].y, kf[j].y);
            }
    }

    float* Sout = g_S + ((size_t)(b * HH + h) * TT + qt * 128 + ty * 8) * TT
                + kt * 64 + tx * 4;
    #pragma unroll
    for (int i = 0; i < 8; i++) {
        float4 v = make_float4(hsum2(acc[i][0]), hsum2(acc[i][1]),
                               hsum2(acc[i][2]), hsum2(acc[i][3]));
        *(float4*)&Sout[(size_t)i * TT] = v;
    }
}

// ---------------- sparsemax + sparse AV: 1 warp per score row ---------------
// Staged: 5 full-register Newton warm-up iterations shrink the candidate set
// (roughly halving per iteration), then compact {z > tau} to smem and finish
// Newton + AV on the compact list. Exact fallback if the list overflows.
__global__ __launch_bounds__(256)
void spmax_av_kernel() {
    __shared__ float sVal[8 * CAND_CAP];           // 16 KB
    __shared__ unsigned short sKey[8 * CAND_CAP];  // 8 KB
    int wid = threadIdx.x >> 5, lane = threadIdx.x & 31;
    int rid = blockIdx.x * 8 + wid;               // [0, NROWS)
    int b = rid >> 13, h = (rid >> 11) & 3, q = rid & 2047;

    const float4* Srow = (const float4*)(g_S + (size_t)rid * TT);
    const uchar4* pad4 = (const uchar4*)(g_pad + b * TT);

    // load row: z[it*4+j] holds key it*128 + lane*4 + j
    float z[64];
    float zmax = -3e38f;
    #pragma unroll
    for (int it = 0; it < 16; it++) {
        float4 sv = Srow[it * 32 + lane];
        uchar4 p = pad4[it * 32 + lane];
        float z0 = p.x ? NEGV : sv.x;
        float z1 = p.y ? NEGV : sv.y;
        float z2 = p.z ? NEGV : sv.z;
        float z3 = p.w ? NEGV : sv.w;
        z[it * 4 + 0] = z0; z[it * 4 + 1] = z1;
        z[it * 4 + 2] = z2; z[it * 4 + 3] = z3;
        zmax = fmaxf(fmaxf(fmaxf(zmax, z0), fmaxf(z1, z2)), z3);
    }
    #pragma unroll
    for (int o = 16; o; o >>= 1) zmax = fmaxf(zmax, __shfl_xor_sync(0xffffffffu, zmax, o));

    // ---- Newton warm-up: 5 full-register iterations (tau stays <= tau*) ----
    float tau = zmax - 1.0f;
    #pragma unroll 1
    for (int it = 0; it < 5; it++) {
        float s = 0.f, c = 0.f;
        #pragma unroll
        for (int i = 0; i < 64; i++) {
            if (z[i] > tau) { s += z[i]; c += 1.0f; }
        }
        #pragma unroll
        for (int o = 16; o; o >>= 1) {
            s += __shfl_xor_sync(0xffffffffu, s, o);
            c += __shfl_xor_sync(0xffffffffu, c, o);
        }
        float nt = (s - 1.0f) / c;
        if (nt == tau) break;
        tau = nt;
    }

    // ---- candidate compaction: support subset of {z > tau} ----
    int base = wid * CAND_CAP;
    unsigned cnt = 0;
    #pragma unroll
    for (int i = 0; i < 64; i++) {
        bool cand = z[i] > tau;
        unsigned m = __ballot_sync(0xffffffffu, cand);
        if (cand) {
            int pos = cnt + __popc(m & ((1u << lane) - 1u));
            if (pos < CAND_CAP) {
                sVal[base + pos] = z[i];
                sKey[base + pos] = (unsigned short)(((i >> 2) << 7) + (lane << 2) + (i & 3));
            }
        }
        cnt += __popc(m);
    }
    __syncwarp();

    const float* Vb = g_V + ((size_t)(b * HH + h) * TT) * HDIM;
    float2 acc = make_float2(0.f, 0.f);

    if (cnt <= CAND_CAP) {
        // ---- finish Newton on the compact list ----
        int n = (int)cnt;
        #pragma unroll 1
        for (int it = 0; it < 27; it++) {
            float s = 0.f, c = 0.f;
            for (int j = lane; j < n; j += 32) {
                float v = sVal[base + j];
                if (v > tau) { s += v; c += 1.0f; }
            }
            #pragma unroll
            for (int o = 16; o; o >>= 1) {
                s += __shfl_xor_sync(0xffffffffu, s, o);
                c += __shfl_xor_sync(0xffffffffu, c, o);
            }
            float nt = (s - 1.0f) / c;
            if (nt == tau) break;
            tau = nt;
        }
        // ---- AV over compact list (uniform broadcast) ----
        for (int j = 0; j < n; j++) {
            float w = sVal[base + j] - tau;
            if (w > 0.f) {
                int k = sKey[base + j];
                float2 vv = *(const float2*)&Vb[(size_t)k * HDIM + lane * 2];
                acc.x += w * vv.x;
                acc.y += w * vv.y;
            }
        }
    } else {
        // ---- fallback: continue full-register Newton + ballot-pop AV ----
        #pragma unroll 1
        for (int it = 0; it < 27; it++) {
            float s = 0.f, c = 0.f;
            #pragma unroll
            for (int i = 0; i < 64; i++) {
                if (z[i] > tau) { s += z[i]; c += 1.0f; }
            }
            #pragma unroll
            for (int o = 16; o; o >>= 1) {
                s += __shfl_xor_sync(0xffffffffu, s, o);
                c += __shfl_xor_sync(0xffffffffu, c, o);
            }
            float nt = (s - 1.0f) / c;
            if (nt == tau) break;
            tau = nt;
        }
        #pragma unroll
        for (int g = 0; g < 16; g++) {
            #pragma unroll
            for (int j = 0; j < 4; j++) {
                float zz = z[g * 4 + j];
                unsigned m = __ballot_sync(0xffffffffu, zz > tau);
                while (m) {
                    int src = __ffs(m) - 1;
                    m &= m - 1;
                    float w = __shfl_sync(0xffffffffu, zz, src) - tau;
                    int k = g * 128 + src * 4 + j;
                    float2 v = *(const float2*)&Vb[(size_t)k * HDIM + lane * 2];
                    acc.x += w * v.x;
                    acc.y += w * v.y;
                }
            }
        }
    }
    *(float2*)&g_attn[((size_t)b * TT + q) * DD + h * HDIM + lane * 2] = acc;
}

// ---------------- out-proj + residual + LayerNorm (known-good) --------------
__global__ __launch_bounds__(256)
void outproj_ln_kernel(const float* __restrict__ x,
                       const float* __restrict__ Wo,
                       const float* __restrict__ gamma,
                       const float* __restrict__ beta,
                       float* __restrict__ out) {
    __shared__ float sA[16][DD];
    __shared__ float sY[16][DD + 1];
    __shared__ float sMu[16], sRs[16];
    int n0 = blockIdx.x * 16;
    int tid = threadIdx.x;              // output column j

    for (int i = tid; i < 16 * 64; i += 256) {
        int r = i >> 6, c4 = (i & 63) * 4;
        *(float4*)&sA[r][c4] = *(const float4*)&g_attn[((size_t)n0 + r) * DD + c4];
    }
    __syncthreads();

    unsigned long long acc2[16] = {};
    const ulonglong2* wrow = (const ulonglong2*)(Wo + (size_t)tid * DD);
    #pragma unroll 4
    for (int c = 0; c < 64; c++) {
        ulonglong2 w = wrow[c];
        #pragma unroll
        for (int r = 0; r < 16; r++) {
            ulonglong2 a = *(const ulonglong2*)&sA[r][c * 4];
            ffma2(acc2[r], w.x, a.x);
            ffma2(acc2[r], w.y, a.y);
        }
    }
    #pragma unroll
    for (int r = 0; r < 16; r++)
        sY[r][tid] = hsum2(acc2[r]) + x[((size_t)n0 + r) * DD + tid];
    __syncthreads();

    int wid = tid >> 5, lane = tid & 31;
    for (int rr = 0; rr < 2; rr++) {
        int r = wid * 2 + rr;
        float s = 0.f, s2 = 0.f;
        #pragma unroll
        for (int i = 0; i < 8; i++) {
            float v = sY[r][lane * 8 + i];
            s += v; s2 += v * v;
        }
        #pragma unroll
        for (int o = 16; o; o >>= 1) {
            s  += __shfl_xor_sync(0xffffffffu, s, o);
            s2 += __shfl_xor_sync(0xffffffffu, s2, o);
        }
        if (lane == 0) {
            float mu = s * (1.0f / DD);
            sMu[r] = mu;
            sRs[r] = rsqrtf(s2 * (1.0f / DD) - mu * mu + EPSV);
        }
    }
    __syncthreads();
    float g = gamma[tid], bt = beta[tid];
    #pragma unroll
    for (int r = 0; r < 16; r++)
        out[((size_t)n0 + r) * DD + tid] = (sY[r][tid] - sMu[r]) * sRs[r] * g + bt;
}

// ---------------- launch ----------------------------------------------------
extern "C" void kernel_launch(void* const* d_in, const int* in_sizes, int n_in,
                              void* d_out, int out_size) {
    const float* x     = (const float*)d_in[0];
    const void*  mask  = d_in[1];
    const float* Wq    = (const float*)d_in[2];
    const float* Wk    = (const float*)d_in[3];
    const float* Wv    = (const float*)d_in[4];
    const float* Wo    = (const float*)d_in[5];
    const float* gamma = (const float*)d_in[6];
    const float* beta  = (const float*)d_in[7];
    float* out = (float*)d_out;

    mask_prep_kernel<<<1, 256>>>(mask);
    qkv_proj_kernel<<<dim3(NT / 64, HH, 3), 256>>>(x, Wq, Wk, Wv);
    score_kernel<<<dim3(512, HH, BB), 256>>>();
    spmax_av_kernel<<<NROWS / 8, 256>>>();
    outproj_ln_kernel<<<NT / 16, 256>>>(x, Wo, gamma, beta, out);
}

// round 13
// speedup vs baseline: 2.9121x; 1.1002x over previous
#include <cuda_runtime.h>
#include <cuda_bf16.h>
#include <mma.h>
#include <cstdint>

using namespace nvcuda;

#define BB 8
#define TT 2048
#define DD 256
#define HH 4
#define HDIM 64
#define NT (BB*TT)           // 16384 rows
#define NROWS (BB*HH*TT)     // 65536 attention score rows
#define NEGV (-1e9f)
#define EPSV 1e-5f
#define CAND_CAP 512
#define QLDM 72              // bf16 smem leading dim (mult of 8)

// ---------------- device scratch (module-load allocated) --------------------
__device__ unsigned short g_Qh[BB*HH*TT*HDIM];   // bf16 hi of Q/8
__device__ unsigned short g_Ql[BB*HH*TT*HDIM];   // bf16 lo of Q/8
__device__ unsigned short g_Kh[BB*HH*TT*HDIM];   // bf16 hi of K
__device__ unsigned short g_Kl[BB*HH*TT*HDIM];   // bf16 lo of K
__device__ float g_V[BB*HH*TT*HDIM];
__device__ float g_S[(size_t)BB*HH*TT*TT];       // 512 MiB score scratch
__device__ float g_attn[NT*DD];
__device__ unsigned char g_pad[NT];

// ---------------- packed fp32x2 helpers -------------------------------------
union F2U { unsigned long long u; float2 f; };

__device__ __forceinline__ void ffma2(unsigned long long& acc,
                                      unsigned long long a, unsigned long long b) {
    asm("fma.rn.f32x2 %0, %1, %2, %0;" : "+l"(acc) : "l"(a), "l"(b));
}
__device__ __forceinline__ float hsum2(unsigned long long u) {
    F2U t; t.u = u; return t.f.x + t.f.y;
}

// ---------------- mask dtype detection + expansion --------------------------
__global__ void mask_prep_kernel(const void* __restrict__ maskraw) {
    __shared__ int cntOff, cnt3F, mode;
    const unsigned char* b = (const unsigned char*)maskraw;
    int tid = threadIdx.x;
    if (tid == 0) { cntOff = 0; cnt3F = 0; }
    __syncthreads();
    int lo = 0, l3 = 0;
    for (int i = tid; i < NT; i += blockDim.x) {
        unsigned char v = b[i];
        if ((i & 3) != 0 && v != 0) lo++;
        if ((i & 3) == 3 && v == 0x3F) l3++;
    }
    atomicAdd(&cntOff, lo);
    atomicAdd(&cnt3F, l3);
    __syncthreads();
    if (tid == 0) {
        if (cnt3F > 0) mode = 2;            // float32
        else if (cntOff > 0) mode = 0;      // uint8 / bool
        else mode = 1;                      // int32
    }
    __syncthreads();
    int m = mode;
    for (int i = tid; i < NT; i += blockDim.x) {
        unsigned char p;
        if (m == 0)      p = (b[i] != 0);
        else if (m == 1) p = (((const int*)maskraw)[i] != 0);
        else             p = (((const float*)maskraw)[i] != 0.0f);
        g_pad[i] = p;
    }
}

// ---------------- QKV projection: emits bf16 hi/lo for Q,K; f32 for V -------
__global__ __launch_bounds__(256)
void qkv_proj_kernel(const float* __restrict__ x,
                     const float* __restrict__ Wq,
                     const float* __restrict__ Wk,
                     const float* __restrict__ Wv) {
    __shared__ float4 Xs4[512];   // 64 rows x 8 chunks
    __shared__ float4 Ws4[512];
    int bz = blockIdx.z;
    const float* W = (bz == 0) ? Wq : (bz == 1 ? Wk : Wv);
    int n0 = blockIdx.x * 64;
    int h  = blockIdx.y;
    int j0 = h * 64;
    int tid = threadIdx.x;
    int tx = tid & 15, ty = tid >> 4;

    int f0 = tid * 2;
    int lr = f0 >> 3, lc = f0 & 7;
    int wxor = ((lr >> 2) & 7) ^ ((lr & 3) << 1);

    const float4* xg = (const float4*)&x[(size_t)(n0 + lr) * DD];
    const float4* wg = (const float4*)&W[(size_t)(j0 + lr) * DD];
    float4 px0 = xg[lc], px1 = xg[lc + 1];
    float4 pw0 = wg[lc], pw1 = wg[lc + 1];

    unsigned long long acc[4][4] = {};

    for (int kk = 0; kk < DD; kk += 32) {
        __syncthreads();
        Xs4[lr * 8 + lc]              = px0;
        Xs4[lr * 8 + lc + 1]          = px1;
        Ws4[lr * 8 + (lc ^ wxor)]     = pw0;
        Ws4[lr * 8 + ((lc + 1) ^ wxor)] = pw1;
        if (kk + 32 < DD) {
            int o = (kk + 32) >> 2;
            px0 = xg[o + lc]; px1 = xg[o + lc + 1];
            pw0 = wg[o + lc]; pw1 = wg[o + lc + 1];
        }
        __syncthreads();
        #pragma unroll
        for (int c = 0; c < 8; c++) {
            ulonglong2 xs[4], ws[4];
            #pragma unroll
            for (int i = 0; i < 4; i++)
                xs[i] = *(const ulonglong2*)&Xs4[(ty * 4 + i) * 8 + c];
            #pragma unroll
            for (int j = 0; j < 4; j++)
                ws[j] = *(const ulonglong2*)&Ws4[(tx * 4 + j) * 8 +
                                                 (c ^ (tx & 7) ^ (j << 1))];
            #pragma unroll
            for (int i = 0; i < 4; i++)
                #pragma unroll
                for (int j = 0; j < 4; j++) {
                    ffma2(acc[i][j], xs[i].x, ws[j].x);
                    ffma2(acc[i][j], xs[i].y, ws[j].y);
                }
        }
    }
    float sc = (bz == 0) ? 0.125f : 1.0f;
    #pragma unroll
    for (int i = 0; i < 4; i++) {
        int n = n0 + ty * 4 + i;
        int bi = n >> 11, t = n & (TT - 1);
        size_t off = (((size_t)bi * HH + h) * TT + t) * HDIM + tx * 4;
        float4 v = make_float4(hsum2(acc[i][0]), hsum2(acc[i][1]),
                               hsum2(acc[i][2]), hsum2(acc[i][3]));
        if (bz == 2) {
            *(float4*)(g_V + off) = v;
        } else {
            float a0 = v.x * sc, a1 = v.y * sc, a2 = v.z * sc, a3 = v.w * sc;
            __nv_bfloat16 h0 = __float2bfloat16(a0), h1 = __float2bfloat16(a1);
            __nv_bfloat16 h2 = __float2bfloat16(a2), h3 = __float2bfloat16(a3);
            __nv_bfloat16 l0 = __float2bfloat16(a0 - __bfloat162float(h0));
            __nv_bfloat16 l1 = __float2bfloat16(a1 - __bfloat162float(h1));
            __nv_bfloat16 l2 = __float2bfloat16(a2 - __bfloat162float(h2));
            __nv_bfloat16 l3 = __float2bfloat16(a3 - __bfloat162float(h3));
            ushort4 hv = make_ushort4(__bfloat16_as_ushort(h0), __bfloat16_as_ushort(h1),
                                      __bfloat16_as_ushort(h2), __bfloat16_as_ushort(h3));
            ushort4 lv = make_ushort4(__bfloat16_as_ushort(l0), __bfloat16_as_ushort(l1),
                                      __bfloat16_as_ushort(l2), __bfloat16_as_ushort(l3));
            unsigned short* H = (bz == 0) ? g_Qh : g_Kh;
            unsigned short* L = (bz == 0) ? g_Ql : g_Kl;
            *(ushort4*)(H + off) = hv;
            *(ushort4*)(L + off) = lv;
        }
    }
}

// ---------------- score GEMM on wmma/HMMA: S = Qs K^T (bf16 hi/lo split) ----
// Per CTA: one 128-query tile, loop 16 k-tiles of 128 keys. 8 warps in 4x2
// (q x k); each warp computes 32q x 64k. 3 passes: Qh*Kh + Qh*Kl + Ql*Kh.
// NOTE: a row is 64 bf16 = 16 ushort4 chunks -> row stride 16 in ushort4.
#define SMEM_WMMA_BYTES (4 * 128 * QLDM * 2)   // 73728

__global__ __launch_bounds__(256)
void score_wmma_kernel() {
    extern __shared__ __align__(128) __nv_bfloat16 sm[];
    __nv_bfloat16* sQh = sm;
    __nv_bfloat16* sQl = sm + 128 * QLDM;
    __nv_bfloat16* sKh = sm + 2 * 128 * QLDM;
    __nv_bfloat16* sKl = sm + 3 * 128 * QLDM;

    int tid = threadIdx.x, wid = tid >> 5;
    int qt = blockIdx.x, h = blockIdx.y, b = blockIdx.z;
    size_t bh = (size_t)b * HH + h;

    const ushort4* Qhg = (const ushort4*)(g_Qh + (bh * TT + (size_t)qt * 128) * HDIM);
    const ushort4* Qlg = (const ushort4*)(g_Ql + (bh * TT + (size_t)qt * 128) * HDIM);
    const ushort4* Khg = (const ushort4*)(g_Kh + bh * TT * HDIM);
    const ushort4* Klg = (const ushort4*)(g_Kl + bh * TT * HDIM);

    // ---- load Q tile hi/lo: 128 rows x 64 bf16 (16 ushort4/row), ldm QLDM --
    {
        int r = tid >> 1, c0 = (tid & 1) * 8;
        #pragma unroll
        for (int c = 0; c < 8; c++) {
            *(ushort4*)(sQh + r * QLDM + (c0 + c) * 4) = Qhg[r * 16 + c0 + c];
            *(ushort4*)(sQl + r * QLDM + (c0 + c) * 4) = Qlg[r * 16 + c0 + c];
        }
    }

    int wm = wid & 3;      // 32-query block within tile
    int wn = wid >> 2;     // 64-key block within tile
    float* Sbase = g_S + (bh * TT + (size_t)qt * 128) * TT;

    for (int kt = 0; kt < 16; kt++) {
        __syncthreads();
        {   // load K tile hi/lo (row stride 16 ushort4)
            int r = tid >> 1, c0 = (tid & 1) * 8;
            const ushort4* kh = Khg + ((size_t)kt * 128 + r) * 16;
            const ushort4* kl = Klg + ((size_t)kt * 128 + r) * 16;
            #pragma unroll
            for (int c = 0; c < 8; c++) {
                *(ushort4*)(sKh + r * QLDM + (c0 + c) * 4) = kh[c0 + c];
                *(ushort4*)(sKl + r * QLDM + (c0 + c) * 4) = kl[c0 + c];
            }
        }
        __syncthreads();

        wmma::fragment<wmma::accumulator, 16, 16, 16, float> acc[2][4];
        #pragma unroll
        for (int i = 0; i < 2; i++)
            #pragma unroll
            for (int j = 0; j < 4; j++)
                wmma::fill_fragment(acc[i][j], 0.0f);

        #pragma unroll
        for (int ks = 0; ks < 4; ks++) {
            wmma::fragment<wmma::matrix_a, 16, 16, 16, __nv_bfloat16, wmma::row_major> ah[2], al[2];
            #pragma unroll
            for (int i = 0; i < 2; i++) {
                wmma::load_matrix_sync(ah[i], sQh + (wm * 32 + i * 16) * QLDM + ks * 16, QLDM);
                wmma::load_matrix_sync(al[i], sQl + (wm * 32 + i * 16) * QLDM + ks * 16, QLDM);
            }
            #pragma unroll
            for (int j = 0; j < 4; j++) {
                wmma::fragment<wmma::matrix_b, 16, 16, 16, __nv_bfloat16, wmma::col_major> bhf, blf;
                wmma::load_matrix_sync(bhf, sKh + (wn * 64 + j * 16) * QLDM + ks * 16, QLDM);
                wmma::load_matrix_sync(blf, sKl + (wn * 64 + j * 16) * QLDM + ks * 16, QLDM);
                #pragma unroll
                for (int i = 0; i < 2; i++) {
                    wmma::mma_sync(acc[i][j], ah[i], bhf, acc[i][j]);
                    wmma::mma_sync(acc[i][j], ah[i], blf, acc[i][j]);
                    wmma::mma_sync(acc[i][j], al[i], bhf, acc[i][j]);
                }
            }
        }
        #pragma unroll
        for (int i = 0; i < 2; i++)
            #pragma unroll
            for (int j = 0; j < 4; j++)
                wmma::store_matrix_sync(
                    Sbase + (size_t)(wm * 32 + i * 16) * TT + kt * 128 + wn * 64 + j * 16,
                    acc[i][j], TT, wmma::mem_row_major);
    }
}

// ---------------- sparsemax + sparse AV (round-10, unchanged) ---------------
__global__ __launch_bounds__(256)
void spmax_av_kernel() {
    __shared__ float sVal[8 * CAND_CAP];           // 16 KB
    __shared__ unsigned short sKey[8 * CAND_CAP];  // 8 KB
    int wid = threadIdx.x >> 5, lane = threadIdx.x & 31;
    int rid = blockIdx.x * 8 + wid;               // [0, NROWS)
    int b = rid >> 13, h = (rid >> 11) & 3, q = rid & 2047;

    const float4* Srow = (const float4*)(g_S + (size_t)rid * TT);
    const uchar4* pad4 = (const uchar4*)(g_pad + b * TT);

    float z[64];
    float zmax = -3e38f;
    #pragma unroll
    for (int it = 0; it < 16; it++) {
        float4 sv = Srow[it * 32 + lane];
        uchar4 p = pad4[it * 32 + lane];
        float z0 = p.x ? NEGV : sv.x;
        float z1 = p.y ? NEGV : sv.y;
        float z2 = p.z ? NEGV : sv.z;
        float z3 = p.w ? NEGV : sv.w;
        z[it * 4 + 0] = z0; z[it * 4 + 1] = z1;
        z[it * 4 + 2] = z2; z[it * 4 + 3] = z3;
        zmax = fmaxf(fmaxf(fmaxf(zmax, z0), fmaxf(z1, z2)), z3);
    }
    #pragma unroll
    for (int o = 16; o; o >>= 1) zmax = fmaxf(zmax, __shfl_xor_sync(0xffffffffu, zmax, o));

    float tau = zmax - 1.0f;
    #pragma unroll 1
    for (int it = 0; it < 5; it++) {
        float s = 0.f, c = 0.f;
        #pragma unroll
        for (int i = 0; i < 64; i++) {
            if (z[i] > tau) { s += z[i]; c += 1.0f; }
        }
        #pragma unroll
        for (int o = 16; o; o >>= 1) {
            s += __shfl_xor_sync(0xffffffffu, s, o);
            c += __shfl_xor_sync(0xffffffffu, c, o);
        }
        float nt = (s - 1.0f) / c;
        if (nt == tau) break;
        tau = nt;
    }

    int base = wid * CAND_CAP;
    unsigned cnt = 0;
    #pragma unroll
    for (int i = 0; i < 64; i++) {
        bool cand = z[i] > tau;
        unsigned m = __ballot_sync(0xffffffffu, cand);
        if (cand) {
            int pos = cnt + __popc(m & ((1u << lane) - 1u));
            if (pos < CAND_CAP) {
                sVal[base + pos] = z[i];
                sKey[base + pos] = (unsigned short)(((i >> 2) << 7) + (lane << 2) + (i & 3));
            }
        }
        cnt += __popc(m);
    }
    __syncwarp();

    const float* Vb = g_V + ((size_t)(b * HH + h) * TT) * HDIM;
    float2 acc = make_float2(0.f, 0.f);

    if (cnt <= CAND_CAP) {
        int n = (int)cnt;
        #pragma unroll 1
        for (int it = 0; it < 27; it++) {
            float s = 0.f, c = 0.f;
            for (int j = lane; j < n; j += 32) {
                float v = sVal[base + j];
                if (v > tau) { s += v; c += 1.0f; }
            }
            #pragma unroll
            for (int o = 16; o; o >>= 1) {
                s += __shfl_xor_sync(0xffffffffu, s, o);
                c += __shfl_xor_sync(0xffffffffu, c, o);
            }
            float nt = (s - 1.0f) / c;
            if (nt == tau) break;
            tau = nt;
        }
        for (int j = 0; j < n; j++) {
            float w = sVal[base + j] - tau;
            if (w > 0.f) {
                int k = sKey[base + j];
                float2 vv = *(const float2*)&Vb[(size_t)k * HDIM + lane * 2];
                acc.x += w * vv.x;
                acc.y += w * vv.y;
            }
        }
    } else {
        #pragma unroll 1
        for (int it = 0; it < 27; it++) {
            float s = 0.f, c = 0.f;
            #pragma unroll
            for (int i = 0; i < 64; i++) {
                if (z[i] > tau) { s += z[i]; c += 1.0f; }
            }
            #pragma unroll
            for (int o = 16; o; o >>= 1) {
                s += __shfl_xor_sync(0xffffffffu, s, o);
                c += __shfl_xor_sync(0xffffffffu, c, o);
            }
            float nt = (s - 1.0f) / c;
            if (nt == tau) break;
            tau = nt;
        }
        #pragma unroll
        for (int g = 0; g < 16; g++) {
            #pragma unroll
            for (int j = 0; j < 4; j++) {
                float zz = z[g * 4 + j];
                unsigned m = __ballot_sync(0xffffffffu, zz > tau);
                while (m) {
                    int src = __ffs(m) - 1;
                    m &= m - 1;
                    float w = __shfl_sync(0xffffffffu, zz, src) - tau;
                    int k = g * 128 + src * 4 + j;
                    float2 v = *(const float2*)&Vb[(size_t)k * HDIM + lane * 2];
                    acc.x += w * v.x;
                    acc.y += w * v.y;
                }
            }
        }
    }
    *(float2*)&g_attn[((size_t)b * TT + q) * DD + h * HDIM + lane * 2] = acc;
}

// ---------------- out-proj + residual + LayerNorm (known-good) --------------
__global__ __launch_bounds__(256)
void outproj_ln_kernel(const float* __restrict__ x,
                       const float* __restrict__ Wo,
                       const float* __restrict__ gamma,
                       const float* __restrict__ beta,
                       float* __restrict__ out) {
    __shared__ float sA[16][DD];
    __shared__ float sY[16][DD + 1];
    __shared__ float sMu[16], sRs[16];
    int n0 = blockIdx.x * 16;
    int tid = threadIdx.x;              // output column j

    for (int i = tid; i < 16 * 64; i += 256) {
        int r = i >> 6, c4 = (i & 63) * 4;
        *(float4*)&sA[r][c4] = *(const float4*)&g_attn[((size_t)n0 + r) * DD + c4];
    }
    __syncthreads();

    unsigned long long acc2[16] = {};
    const ulonglong2* wrow = (const ulonglong2*)(Wo + (size_t)tid * DD);
    #pragma unroll 4
    for (int c = 0; c < 64; c++) {
        ulonglong2 w = wrow[c];
        #pragma unroll
        for (int r = 0; r < 16; r++) {
            ulonglong2 a = *(const ulonglong2*)&sA[r][c * 4];
            ffma2(acc2[r], w.x, a.x);
            ffma2(acc2[r], w.y, a.y);
        }
    }
    #pragma unroll
    for (int r = 0; r < 16; r++)
        sY[r][tid] = hsum2(acc2[r]) + x[((size_t)n0 + r) * DD + tid];
    __syncthreads();

    int wid = tid >> 5, lane = tid & 31;
    for (int rr = 0; rr < 2; rr++) {
        int r = wid * 2 + rr;
        float s = 0.f, s2 = 0.f;
        #pragma unroll
        for (int i = 0; i < 8; i++) {
            float v = sY[r][lane * 8 + i];
            s += v; s2 += v * v;
        }
        #pragma unroll
        for (int o = 16; o; o >>= 1) {
            s  += __shfl_xor_sync(0xffffffffu, s, o);
            s2 += __shfl_xor_sync(0xffffffffu, s2, o);
        }
        if (lane == 0) {
            float mu = s * (1.0f / DD);
            sMu[r] = mu;
            sRs[r] = rsqrtf(s2 * (1.0f / DD) - mu * mu + EPSV);
        }
    }
    __syncthreads();
    float g = gamma[tid], bt = beta[tid];
    #pragma unroll
    for (int r = 0; r < 16; r++)
        out[((size_t)n0 + r) * DD + tid] = (sY[r][tid] - sMu[r]) * sRs[r] * g + bt;
}

// ---------------- launch ----------------------------------------------------
extern "C" void kernel_launch(void* const* d_in, const int* in_sizes, int n_in,
                              void* d_out, int out_size) {
    const float* x     = (const float*)d_in[0];
    const void*  mask  = d_in[1];
    const float* Wq    = (const float*)d_in[2];
    const float* Wk    = (const float*)d_in[3];
    const float* Wv    = (const float*)d_in[4];
    const float* Wo    = (const float*)d_in[5];
    const float* gamma = (const float*)d_in[6];
    const float* beta  = (const float*)d_in[7];
    float* out = (float*)d_out;

    cudaFuncSetAttribute(score_wmma_kernel,
                         cudaFuncAttributeMaxDynamicSharedMemorySize, SMEM_WMMA_BYTES);

    mask_prep_kernel<<<1, 256>>>(mask);
    qkv_proj_kernel<<<dim3(NT / 64, HH, 3), 256>>>(x, Wq, Wk, Wv);
    score_wmma_kernel<<<dim3(16, HH, BB), 256, SMEM_WMMA_BYTES>>>();
    spmax_av_kernel<<<NROWS / 8, 256>>>();
    outproj_ln_kernel<<<NT / 16, 256>>>(x, Wo, gamma, beta, out);
}

// round 14
// speedup vs baseline: 3.0616x; 1.0513x over previous
#include <cuda_runtime.h>
#include <cuda_bf16.h>
#include <mma.h>
#include <cstdint>

using namespace nvcuda;

#define BB 8
#define TT 2048
#define DD 256
#define HH 4
#define HDIM 64
#define NT (BB*TT)           // 16384 rows
#define NROWS (BB*HH*TT)     // 65536 attention score rows
#define NEGV (-1e9f)
#define EPSV 1e-5f
#define CAND_CAP 512
#define QLDM 72              // bf16 smem leading dim (mult of 8)

// ---------------- device scratch (module-load allocated) --------------------
__device__ unsigned short g_Xh[NT*DD];           // bf16 hi of x
__device__ unsigned short g_Xl[NT*DD];           // bf16 lo of x
__device__ unsigned short g_Wh[3*DD*DD];         // bf16 hi of Wq,Wk,Wv
__device__ unsigned short g_Wl[3*DD*DD];         // bf16 lo
__device__ unsigned short g_Qh[BB*HH*TT*HDIM];   // bf16 hi of Q/8
__device__ unsigned short g_Ql[BB*HH*TT*HDIM];   // bf16 lo of Q/8
__device__ unsigned short g_Kh[BB*HH*TT*HDIM];   // bf16 hi of K
__device__ unsigned short g_Kl[BB*HH*TT*HDIM];   // bf16 lo of K
__device__ float g_V[BB*HH*TT*HDIM];
__device__ float g_S[(size_t)BB*HH*TT*TT];       // 512 MiB score scratch
__device__ float g_attn[NT*DD];
__device__ unsigned char g_pad[NT];

// ---------------- packed fp32x2 helpers -------------------------------------
union F2U { unsigned long long u; float2 f; };

__device__ __forceinline__ void ffma2(unsigned long long& acc,
                                      unsigned long long a, unsigned long long b) {
    asm("fma.rn.f32x2 %0, %1, %2, %0;" : "+l"(acc) : "l"(a), "l"(b));
}
__device__ __forceinline__ float hsum2(unsigned long long u) {
    F2U t; t.u = u; return t.f.x + t.f.y;
}

// hi/lo bf16 split of a float4
__device__ __forceinline__ void split4(float4 v, ushort4& hv, ushort4& lv) {
    __nv_bfloat16 h0 = __float2bfloat16(v.x), h1 = __float2bfloat16(v.y);
    __nv_bfloat16 h2 = __float2bfloat16(v.z), h3 = __float2bfloat16(v.w);
    __nv_bfloat16 l0 = __float2bfloat16(v.x - __bfloat162float(h0));
    __nv_bfloat16 l1 = __float2bfloat16(v.y - __bfloat162float(h1));
    __nv_bfloat16 l2 = __float2bfloat16(v.z - __bfloat162float(h2));
    __nv_bfloat16 l3 = __float2bfloat16(v.w - __bfloat162float(h3));
    hv = make_ushort4(__bfloat16_as_ushort(h0), __bfloat16_as_ushort(h1),
                      __bfloat16_as_ushort(h2), __bfloat16_as_ushort(h3));
    lv = make_ushort4(__bfloat16_as_ushort(l0), __bfloat16_as_ushort(l1),
                      __bfloat16_as_ushort(l2), __bfloat16_as_ushort(l3));
}

// ---------------- mask dtype detection + expansion --------------------------
__global__ void mask_prep_kernel(const void* __restrict__ maskraw) {
    __shared__ int cntOff, cnt3F, mode;
    const unsigned char* b = (const unsigned char*)maskraw;
    int tid = threadIdx.x;
    if (tid == 0) { cntOff = 0; cnt3F = 0; }
    __syncthreads();
    int lo = 0, l3 = 0;
    for (int i = tid; i < NT; i += blockDim.x) {
        unsigned char v = b[i];
        if ((i & 3) != 0 && v != 0) lo++;
        if ((i & 3) == 3 && v == 0x3F) l3++;
    }
    atomicAdd(&cntOff, lo);
    atomicAdd(&cnt3F, l3);
    __syncthreads();
    if (tid == 0) {
        if (cnt3F > 0) mode = 2;            // float32
        else if (cntOff > 0) mode = 0;      // uint8 / bool
        else mode = 1;                      // int32
    }
    __syncthreads();
    int m = mode;
    for (int i = tid; i < NT; i += blockDim.x) {
        unsigned char p;
        if (m == 0)      p = (b[i] != 0);
        else if (m == 1) p = (((const int*)maskraw)[i] != 0);
        else             p = (((const float*)maskraw)[i] != 0.0f);
        g_pad[i] = p;
    }
}

// ---------------- decompose x and W into bf16 hi/lo --------------------------
#define NX4 (NT*DD/4)        // 1048576 float4 of x
#define NW4 (3*DD*DD/4)      // 49152 float4 of W
__global__ __launch_bounds__(256)
void decompose_kernel(const float* __restrict__ x,
                      const float* __restrict__ Wq,
                      const float* __restrict__ Wk,
                      const float* __restrict__ Wv) {
    int idx = blockIdx.x * 256 + threadIdx.x;
    if (idx < NX4) {
        float4 v = ((const float4*)x)[idx];
        ushort4 hv, lv;
        split4(v, hv, lv);
        ((ushort4*)g_Xh)[idx] = hv;
        ((ushort4*)g_Xl)[idx] = lv;
    } else if (idx < NX4 + NW4) {
        int w = idx - NX4;
        int z = w / (DD * DD / 4), r = w % (DD * DD / 4);
        const float* W = (z == 0) ? Wq : (z == 1 ? Wk : Wv);
        float4 v = ((const float4*)W)[r];
        ushort4 hv, lv;
        split4(v, hv, lv);
        ((ushort4*)g_Wh)[z * (DD * DD / 4) + r] = hv;
        ((ushort4*)g_Wl)[z * (DD * DD / 4) + r] = lv;
    }
}

// ---------------- QKV projection on wmma (bf16 hi/lo, 3 passes) --------------
// Per CTA: 128 rows (n) x 64 cols (j = dims of head h), K = 256 in 4 steps.
// blockIdx = (n-tile, head, z) with z in {Q,K,V}. 8 warps: wm=wid&3 (32-row
// block), wn=wid>>2 (32-col block). Epilogue stages fp32 in smem, then emits
// Q/K bf16 hi/lo (Q pre-scaled 1/8) and V f32 — same formats as before.
#define SMEM_QKV_BYTES ((2*128*QLDM + 2*64*QLDM) * 2)   // 55296

__global__ __launch_bounds__(256)
void qkv_wmma_kernel() {
    extern __shared__ __align__(128) unsigned char smq[];
    __nv_bfloat16* sXh = (__nv_bfloat16*)smq;
    __nv_bfloat16* sXl = sXh + 128 * QLDM;
    __nv_bfloat16* sWh = sXl + 128 * QLDM;
    __nv_bfloat16* sWl = sWh + 64 * QLDM;
    float* stage = (float*)smq;               // aliases sXh/sXl after k-loop

    int tid = threadIdx.x, wid = tid >> 5;
    int n0 = blockIdx.x * 128;
    int h  = blockIdx.y;
    int z  = blockIdx.z;
    int j0 = h * 64;

    const ushort4* Xh4 = (const ushort4*)g_Xh;   // row stride 64 ushort4
    const ushort4* Xl4 = (const ushort4*)g_Xl;
    const ushort4* Wh4 = (const ushort4*)g_Wh + (size_t)z * (DD * DD / 4);
    const ushort4* Wl4 = (const ushort4*)g_Wl + (size_t)z * (DD * DD / 4);

    int wm = wid & 3;       // 32-row block
    int wn = wid >> 2;      // 32-col block
    wmma::fragment<wmma::accumulator, 16, 16, 16, float> acc[2][2];
    #pragma unroll
    for (int i = 0; i < 2; i++)
        #pragma unroll
        for (int j = 0; j < 2; j++)
            wmma::fill_fragment(acc[i][j], 0.0f);

    for (int kt = 0; kt < 4; kt++) {
        __syncthreads();
        {   // X tile: 128 rows x 64 bf16 = 16 ushort4/row
            int r = tid >> 1, c0 = (tid & 1) * 8;
            #pragma unroll
            for (int c = 0; c < 8; c++) {
                *(ushort4*)(sXh + r * QLDM + (c0 + c) * 4) =
                    Xh4[(size_t)(n0 + r) * 64 + kt * 16 + c0 + c];
                *(ushort4*)(sXl + r * QLDM + (c0 + c) * 4) =
                    Xl4[(size_t)(n0 + r) * 64 + kt * 16 + c0 + c];
            }
        }
        {   // W tile: 64 rows (j) x 64 bf16; W row stride 64 ushort4
            int r = tid >> 2, c0 = (tid & 3) * 4;
            #pragma unroll
            for (int c = 0; c < 4; c++) {
                *(ushort4*)(sWh + r * QLDM + (c0 + c) * 4) =
                    Wh4[(size_t)(j0 + r) * 64 + kt * 16 + c0 + c];
                *(ushort4*)(sWl + r * QLDM + (c0 + c) * 4) =
                    Wl4[(size_t)(j0 + r) * 64 + kt * 16 + c0 + c];
            }
        }
        __syncthreads();

        #pragma unroll
        for (int ks = 0; ks < 4; ks++) {
            wmma::fragment<wmma::matrix_a, 16, 16, 16, __nv_bfloat16, wmma::row_major> ah[2], al[2];
            #pragma unroll
            for (int i = 0; i < 2; i++) {
                wmma::load_matrix_sync(ah[i], sXh + (wm * 32 + i * 16) * QLDM + ks * 16, QLDM);
                wmma::load_matrix_sync(al[i], sXl + (wm * 32 + i * 16) * QLDM + ks * 16, QLDM);
            }
            #pragma unroll
            for (int j = 0; j < 2; j++) {
                wmma::fragment<wmma::matrix_b, 16, 16, 16, __nv_bfloat16, wmma::col_major> bhf, blf;
                wmma::load_matrix_sync(bhf, sWh + (wn * 32 + j * 16) * QLDM + ks * 16, QLDM);
                wmma::load_matrix_sync(blf, sWl + (wn * 32 + j * 16) * QLDM + ks * 16, QLDM);
                #pragma unroll
                for (int i = 0; i < 2; i++) {
                    wmma::mma_sync(acc[i][j], ah[i], bhf, acc[i][j]);
                    wmma::mma_sync(acc[i][j], ah[i], blf, acc[i][j]);
                    wmma::mma_sync(acc[i][j], al[i], bhf, acc[i][j]);
                }
            }
        }
    }
    __syncthreads();   // done reading sX/sW; staging may alias

    #pragma unroll
    for (int i = 0; i < 2; i++)
        #pragma unroll
        for (int j = 0; j < 2; j++)
            wmma::store_matrix_sync(stage + (wm * 32 + i * 16) * 68 + wn * 32 + j * 16,
                                    acc[i][j], 68, wmma::mem_row_major);
    __syncthreads();

    // epilogue: thread -> row r = tid>>1, cols c0..c0+31
    {
        int r = tid >> 1, c0 = (tid & 1) * 32;
        int n = n0 + r;
        int bi = n >> 11, t = n & (TT - 1);
        size_t off = (((size_t)bi * HH + h) * TT + t) * HDIM + c0;
        float sc = (z == 0) ? 0.125f : 1.0f;
        #pragma unroll
        for (int c = 0; c < 8; c++) {
            float4 v = *(float4*)(stage + r * 68 + c0 + c * 4);
            if (z == 2) {
                *(float4*)(g_V + off + c * 4) = v;
            } else {
                v.x *= sc; v.y *= sc; v.z *= sc; v.w *= sc;
                ushort4 hv, lv;
                split4(v, hv, lv);
                unsigned short* H = (z == 0) ? g_Qh : g_Kh;
                unsigned short* L = (z == 0) ? g_Ql : g_Kl;
                *(ushort4*)(H + off + c * 4) = hv;
                *(ushort4*)(L + off + c * 4) = lv;
            }
        }
    }
}

// ---------------- score GEMM on wmma/HMMA (round-13 known-good) -------------
#define SMEM_WMMA_BYTES (4 * 128 * QLDM * 2)   // 73728

__global__ __launch_bounds__(256)
void score_wmma_kernel() {
    extern __shared__ __align__(128) __nv_bfloat16 sm[];
    __nv_bfloat16* sQh = sm;
    __nv_bfloat16* sQl = sm + 128 * QLDM;
    __nv_bfloat16* sKh = sm + 2 * 128 * QLDM;
    __nv_bfloat16* sKl = sm + 3 * 128 * QLDM;

    int tid = threadIdx.x, wid = tid >> 5;
    int qt = blockIdx.x, h = blockIdx.y, b = blockIdx.z;
    size_t bh = (size_t)b * HH + h;

    const ushort4* Qhg = (const ushort4*)(g_Qh + (bh * TT + (size_t)qt * 128) * HDIM);
    const ushort4* Qlg = (const ushort4*)(g_Ql + (bh * TT + (size_t)qt * 128) * HDIM);
    const ushort4* Khg = (const ushort4*)(g_Kh + bh * TT * HDIM);
    const ushort4* Klg = (const ushort4*)(g_Kl + bh * TT * HDIM);

    {
        int r = tid >> 1, c0 = (tid & 1) * 8;
        #pragma unroll
        for (int c = 0; c < 8; c++) {
            *(ushort4*)(sQh + r * QLDM + (c0 + c) * 4) = Qhg[r * 16 + c0 + c];
            *(ushort4*)(sQl + r * QLDM + (c0 + c) * 4) = Qlg[r * 16 + c0 + c];
        }
    }

    int wm = wid & 3;      // 32-query block within tile
    int wn = wid >> 2;     // 64-key block within tile
    float* Sbase = g_S + (bh * TT + (size_t)qt * 128) * TT;

    for (int kt = 0; kt < 16; kt++) {
        __syncthreads();
        {
            int r = tid >> 1, c0 = (tid & 1) * 8;
            const ushort4* kh = Khg + ((size_t)kt * 128 + r) * 16;
            const ushort4* kl = Klg + ((size_t)kt * 128 + r) * 16;
            #pragma unroll
            for (int c = 0; c < 8; c++) {
                *(ushort4*)(sKh + r * QLDM + (c0 + c) * 4) = kh[c0 + c];
                *(ushort4*)(sKl + r * QLDM + (c0 + c) * 4) = kl[c0 + c];
            }
        }
        __syncthreads();

        wmma::fragment<wmma::accumulator, 16, 16, 16, float> acc[2][4];
        #pragma unroll
        for (int i = 0; i < 2; i++)
            #pragma unroll
            for (int j = 0; j < 4; j++)
                wmma::fill_fragment(acc[i][j], 0.0f);

        #pragma unroll
        for (int ks = 0; ks < 4; ks++) {
            wmma::fragment<wmma::matrix_a, 16, 16, 16, __nv_bfloat16, wmma::row_major> ah[2], al[2];
            #pragma unroll
            for (int i = 0; i < 2; i++) {
                wmma::load_matrix_sync(ah[i], sQh + (wm * 32 + i * 16) * QLDM + ks * 16, QLDM);
                wmma::load_matrix_sync(al[i], sQl + (wm * 32 + i * 16) * QLDM + ks * 16, QLDM);
            }
            #pragma unroll
            for (int j = 0; j < 4; j++) {
                wmma::fragment<wmma::matrix_b, 16, 16, 16, __nv_bfloat16, wmma::col_major> bhf, blf;
                wmma::load_matrix_sync(bhf, sKh + (wn * 64 + j * 16) * QLDM + ks * 16, QLDM);
                wmma::load_matrix_sync(blf, sKl + (wn * 64 + j * 16) * QLDM + ks * 16, QLDM);
                #pragma unroll
                for (int i = 0; i < 2; i++) {
                    wmma::mma_sync(acc[i][j], ah[i], bhf, acc[i][j]);
                    wmma::mma_sync(acc[i][j], ah[i], blf, acc[i][j]);
                    wmma::mma_sync(acc[i][j], al[i], bhf, acc[i][j]);
                }
            }
        }
        #pragma unroll
        for (int i = 0; i < 2; i++)
            #pragma unroll
            for (int j = 0; j < 4; j++)
                wmma::store_matrix_sync(
                    Sbase + (size_t)(wm * 32 + i * 16) * TT + kt * 128 + wn * 64 + j * 16,
                    acc[i][j], TT, wmma::mem_row_major);
    }
}

// ---------------- sparsemax + sparse AV (round-10, unchanged) ---------------
__global__ __launch_bounds__(256)
void spmax_av_kernel() {
    __shared__ float sVal[8 * CAND_CAP];           // 16 KB
    __shared__ unsigned short sKey[8 * CAND_CAP];  // 8 KB
    int wid = threadIdx.x >> 5, lane = threadIdx.x & 31;
    int rid = blockIdx.x * 8 + wid;               // [0, NROWS)
    int b = rid >> 13, h = (rid >> 11) & 3, q = rid & 2047;

    const float4* Srow = (const float4*)(g_S + (size_t)rid * TT);
    const uchar4* pad4 = (const uchar4*)(g_pad + b * TT);

    float z[64];
    float zmax = -3e38f;
    #pragma unroll
    for (int it = 0; it < 16; it++) {
        float4 sv = Srow[it * 32 + lane];
        uchar4 p = pad4[it * 32 + lane];
        float z0 = p.x ? NEGV : sv.x;
        float z1 = p.y ? NEGV : sv.y;
        float z2 = p.z ? NEGV : sv.z;
        float z3 = p.w ? NEGV : sv.w;
        z[it * 4 + 0] = z0; z[it * 4 + 1] = z1;
        z[it * 4 + 2] = z2; z[it * 4 + 3] = z3;
        zmax = fmaxf(fmaxf(fmaxf(zmax, z0), fmaxf(z1, z2)), z3);
    }
    #pragma unroll
    for (int o = 16; o; o >>= 1) zmax = fmaxf(zmax, __shfl_xor_sync(0xffffffffu, zmax, o));

    float tau = zmax - 1.0f;
    #pragma unroll 1
    for (int it = 0; it < 5; it++) {
        float s = 0.f, c = 0.f;
        #pragma unroll
        for (int i = 0; i < 64; i++) {
            if (z[i] > tau) { s += z[i]; c += 1.0f; }
        }
        #pragma unroll
        for (int o = 16; o; o >>= 1) {
            s += __shfl_xor_sync(0xffffffffu, s, o);
            c += __shfl_xor_sync(0xffffffffu, c, o);
        }
        float nt = (s - 1.0f) / c;
        if (nt == tau) break;
        tau = nt;
    }

    int base = wid * CAND_CAP;
    unsigned cnt = 0;
    #pragma unroll
    for (int i = 0; i < 64; i++) {
        bool cand = z[i] > tau;
        unsigned m = __ballot_sync(0xffffffffu, cand);
        if (cand) {
            int pos = cnt + __popc(m & ((1u << lane) - 1u));
            if (pos < CAND_CAP) {
                sVal[base + pos] = z[i];
                sKey[base + pos] = (unsigned short)(((i >> 2) << 7) + (lane << 2) + (i & 3));
            }
        }
        cnt += __popc(m);
    }
    __syncwarp();

    const float* Vb = g_V + ((size_t)(b * HH + h) * TT) * HDIM;
    float2 acc = make_float2(0.f, 0.f);

    if (cnt <= CAND_CAP) {
        int n = (int)cnt;
        #pragma unroll 1
        for (int it = 0; it < 27; it++) {
            float s = 0.f, c = 0.f;
            for (int j = lane; j < n; j += 32) {
                float v = sVal[base + j];
                if (v > tau) { s += v; c += 1.0f; }
            }
            #pragma unroll
            for (int o = 16; o; o >>= 1) {
                s += __shfl_xor_sync(0xffffffffu, s, o);
                c += __shfl_xor_sync(0xffffffffu, c, o);
            }
            float nt = (s - 1.0f) / c;
            if (nt == tau) break;
            tau = nt;
        }
        for (int j = 0; j < n; j++) {
            float w = sVal[base + j] - tau;
            if (w > 0.f) {
                int k = sKey[base + j];
                float2 vv = *(const float2*)&Vb[(size_t)k * HDIM + lane * 2];
                acc.x += w * vv.x;
                acc.y += w * vv.y;
            }
        }
    } else {
        #pragma unroll 1
        for (int it = 0; it < 27; it++) {
            float s = 0.f, c = 0.f;
            #pragma unroll
            for (int i = 0; i < 64; i++) {
                if (z[i] > tau) { s += z[i]; c += 1.0f; }
            }
            #pragma unroll
            for (int o = 16; o; o >>= 1) {
                s += __shfl_xor_sync(0xffffffffu, s, o);
                c += __shfl_xor_sync(0xffffffffu, c, o);
            }
            float nt = (s - 1.0f) / c;
            if (nt == tau) break;
            tau = nt;
        }
        #pragma unroll
        for (int g = 0; g < 16; g++) {
            #pragma unroll
            for (int j = 0; j < 4; j++) {
                float zz = z[g * 4 + j];
                unsigned m = __ballot_sync(0xffffffffu, zz > tau);
                while (m) {
                    int src = __ffs(m) - 1;
                    m &= m - 1;
                    float w = __shfl_sync(0xffffffffu, zz, src) - tau;
                    int k = g * 128 + src * 4 + j;
                    float2 v = *(const float2*)&Vb[(size_t)k * HDIM + lane * 2];
                    acc.x += w * v.x;
                    acc.y += w * v.y;
                }
            }
        }
    }
    *(float2*)&g_attn[((size_t)b * TT + q) * DD + h * HDIM + lane * 2] = acc;
}

// ---------------- out-proj + residual + LayerNorm (known-good) --------------
__global__ __launch_bounds__(256)
void outproj_ln_kernel(const float* __restrict__ x,
                       const float* __restrict__ Wo,
                       const float* __restrict__ gamma,
                       const float* __restrict__ beta,
                       float* __restrict__ out) {
    __shared__ float sA[16][DD];
    __shared__ float sY[16][DD + 1];
    __shared__ float sMu[16], sRs[16];
    int n0 = blockIdx.x * 16;
    int tid = threadIdx.x;              // output column j

    for (int i = tid; i < 16 * 64; i += 256) {
        int r = i >> 6, c4 = (i & 63) * 4;
        *(float4*)&sA[r][c4] = *(const float4*)&g_attn[((size_t)n0 + r) * DD + c4];
    }
    __syncthreads();

    unsigned long long acc2[16] = {};
    const ulonglong2* wrow = (const ulonglong2*)(Wo + (size_t)tid * DD);
    #pragma unroll 4
    for (int c = 0; c < 64; c++) {
        ulonglong2 w = wrow[c];
        #pragma unroll
        for (int r = 0; r < 16; r++) {
            ulonglong2 a = *(const ulonglong2*)&sA[r][c * 4];
            ffma2(acc2[r], w.x, a.x);
            ffma2(acc2[r], w.y, a.y);
        }
    }
    #pragma unroll
    for (int r = 0; r < 16; r++)
        sY[r][tid] = hsum2(acc2[r]) + x[((size_t)n0 + r) * DD + tid];
    __syncthreads();

    int wid = tid >> 5, lane = tid & 31;
    for (int rr = 0; rr < 2; rr++) {
        int r = wid * 2 + rr;
        float s = 0.f, s2 = 0.f;
        #pragma unroll
        for (int i = 0; i < 8; i++) {
            float v = sY[r][lane * 8 + i];
            s += v; s2 += v * v;
        }
        #pragma unroll
        for (int o = 16; o; o >>= 1) {
            s  += __shfl_xor_sync(0xffffffffu, s, o);
            s2 += __shfl_xor_sync(0xffffffffu, s2, o);
        }
        if (lane == 0) {
            float mu = s * (1.0f / DD);
            sMu[r] = mu;
            sRs[r] = rsqrtf(s2 * (1.0f / DD) - mu * mu + EPSV);
        }
    }
    __syncthreads();
    float g = gamma[tid], bt = beta[tid];
    #pragma unroll
    for (int r = 0; r < 16; r++)
        out[((size_t)n0 + r) * DD + tid] = (sY[r][tid] - sMu[r]) * sRs[r] * g + bt;
}

// ---------------- launch ----------------------------------------------------
extern "C" void kernel_launch(void* const* d_in, const int* in_sizes, int n_in,
                              void* d_out, int out_size) {
    const float* x     = (const float*)d_in[0];
    const void*  mask  = d_in[1];
    const float* Wq    = (const float*)d_in[2];
    const float* Wk    = (const float*)d_in[3];
    const float* Wv    = (const float*)d_in[4];
    const float* Wo    = (const float*)d_in[5];
    const float* gamma = (const float*)d_in[6];
    const float* beta  = (const float*)d_in[7];
    float* out = (float*)d_out;

    cudaFuncSetAttribute(score_wmma_kernel,
                         cudaFuncAttributeMaxDynamicSharedMemorySize, SMEM_WMMA_BYTES);
    cudaFuncSetAttribute(qkv_wmma_kernel,
                         cudaFuncAttributeMaxDynamicSharedMemorySize, SMEM_QKV_BYTES);

    mask_prep_kernel<<<1, 256>>>(mask);
    decompose_kernel<<<(NX4 + NW4 + 255) / 256, 256>>>(x, Wq, Wk, Wv);
    qkv_wmma_kernel<<<dim3(NT / 128, HH, 3), 256, SMEM_QKV_BYTES>>>();
    score_wmma_kernel<<<dim3(16, HH, BB), 256, SMEM_WMMA_BYTES>>>();
    spmax_av_kernel<<<NROWS / 8, 256>>>();
    outproj_ln_kernel<<<NT / 16, 256>>>(x, Wo, gamma, beta, out);
}

// round 15
// speedup vs baseline: 3.4087x; 1.1134x over previous
#include <cuda_runtime.h>
#include <cuda_bf16.h>
#include <mma.h>
#include <cstdint>

using namespace nvcuda;

#define BB 8
#define TT 2048
#define DD 256
#define HH 4
#define HDIM 64
#define NT (BB*TT)           // 16384 rows
#define NROWS (BB*HH*TT)     // 65536 attention score rows
#define NEGV (-1e9f)
#define EPSV 1e-5f
#define CAND_CAP 512
#define QLDM 72              // bf16 smem leading dim (mult of 8; 144 B row)

// ---------------- device scratch (module-load allocated) --------------------
__device__ unsigned short g_Xh[NT*DD];           // bf16 hi of x
__device__ unsigned short g_Xl[NT*DD];           // bf16 lo of x
__device__ unsigned short g_Wh[3*DD*DD];         // bf16 hi of Wq,Wk,Wv
__device__ unsigned short g_Wl[3*DD*DD];         // bf16 lo
__device__ unsigned short g_Qh[BB*HH*TT*HDIM];   // bf16 hi of Q/8
__device__ unsigned short g_Ql[BB*HH*TT*HDIM];   // bf16 lo of Q/8
__device__ unsigned short g_Kh[BB*HH*TT*HDIM];   // bf16 hi of K
__device__ unsigned short g_Kl[BB*HH*TT*HDIM];   // bf16 lo of K
__device__ float g_V[BB*HH*TT*HDIM];
__device__ float g_S[(size_t)BB*HH*TT*TT];       // 512 MiB score scratch
__device__ float g_attn[NT*DD];
__device__ unsigned char g_pad[NT];

// ---------------- packed fp32x2 helpers -------------------------------------
union F2U { unsigned long long u; float2 f; };

__device__ __forceinline__ void ffma2(unsigned long long& acc,
                                      unsigned long long a, unsigned long long b) {
    asm("fma.rn.f32x2 %0, %1, %2, %0;" : "+l"(acc) : "l"(a), "l"(b));
}
__device__ __forceinline__ float hsum2(unsigned long long u) {
    F2U t; t.u = u; return t.f.x + t.f.y;
}

// hi/lo bf16 split of a float4
__device__ __forceinline__ void split4(float4 v, ushort4& hv, ushort4& lv) {
    __nv_bfloat16 h0 = __float2bfloat16(v.x), h1 = __float2bfloat16(v.y);
    __nv_bfloat16 h2 = __float2bfloat16(v.z), h3 = __float2bfloat16(v.w);
    __nv_bfloat16 l0 = __float2bfloat16(v.x - __bfloat162float(h0));
    __nv_bfloat16 l1 = __float2bfloat16(v.y - __bfloat162float(h1));
    __nv_bfloat16 l2 = __float2bfloat16(v.z - __bfloat162float(h2));
    __nv_bfloat16 l3 = __float2bfloat16(v.w - __bfloat162float(h3));
    hv = make_ushort4(__bfloat16_as_ushort(h0), __bfloat16_as_ushort(h1),
                      __bfloat16_as_ushort(h2), __bfloat16_as_ushort(h3));
    lv = make_ushort4(__bfloat16_as_ushort(l0), __bfloat16_as_ushort(l1),
                      __bfloat16_as_ushort(l2), __bfloat16_as_ushort(l3));
}

__device__ __forceinline__ uint32_t smem_u32(const void* p) {
    uint32_t a;
    asm("{ .reg .u64 t; cvta.to.shared.u64 t, %1; cvt.u32.u64 %0, t; }"
        : "=r"(a) : "l"(p));
    return a;
}
__device__ __forceinline__ void cp_async16(uint32_t dst, const void* src) {
    asm volatile("cp.async.cg.shared.global [%0], [%1], 16;"
                 :: "r"(dst), "l"(src));
}
#define CP_COMMIT() asm volatile("cp.async.commit_group;" ::: "memory")
#define CP_WAIT1()  asm volatile("cp.async.wait_group 1;" ::: "memory")

// ---------------- mask dtype detection + expansion --------------------------
__global__ void mask_prep_kernel(const void* __restrict__ maskraw) {
    __shared__ int cntOff, cnt3F, mode;
    const unsigned char* b = (const unsigned char*)maskraw;
    int tid = threadIdx.x;
    if (tid == 0) { cntOff = 0; cnt3F = 0; }
    __syncthreads();
    int lo = 0, l3 = 0;
    for (int i = tid; i < NT; i += blockDim.x) {
        unsigned char v = b[i];
        if ((i & 3) != 0 && v != 0) lo++;
        if ((i & 3) == 3 && v == 0x3F) l3++;
    }
    atomicAdd(&cntOff, lo);
    atomicAdd(&cnt3F, l3);
    __syncthreads();
    if (tid == 0) {
        if (cnt3F > 0) mode = 2;            // float32
        else if (cntOff > 0) mode = 0;      // uint8 / bool
        else mode = 1;                      // int32
    }
    __syncthreads();
    int m = mode;
    for (int i = tid; i < NT; i += blockDim.x) {
        unsigned char p;
        if (m == 0)      p = (b[i] != 0);
        else if (m == 1) p = (((const int*)maskraw)[i] != 0);
        else             p = (((const float*)maskraw)[i] != 0.0f);
        g_pad[i] = p;
    }
}

// ---------------- decompose x and W into bf16 hi/lo --------------------------
#define NX4 (NT*DD/4)        // 1048576 float4 of x
#define NW4 (3*DD*DD/4)      // 49152 float4 of W
__global__ __launch_bounds__(256)
void decompose_kernel(const float* __restrict__ x,
                      const float* __restrict__ Wq,
                      const float* __restrict__ Wk,
                      const float* __restrict__ Wv) {
    int idx = blockIdx.x * 256 + threadIdx.x;
    if (idx < NX4) {
        float4 v = ((const float4*)x)[idx];
        ushort4 hv, lv;
        split4(v, hv, lv);
        ((ushort4*)g_Xh)[idx] = hv;
        ((ushort4*)g_Xl)[idx] = lv;
    } else if (idx < NX4 + NW4) {
        int w = idx - NX4;
        int z = w / (DD * DD / 4), r = w % (DD * DD / 4);
        const float* W = (z == 0) ? Wq : (z == 1 ? Wk : Wv);
        float4 v = ((const float4*)W)[r];
        ushort4 hv, lv;
        split4(v, hv, lv);
        ((ushort4*)g_Wh)[z * (DD * DD / 4) + r] = hv;
        ((ushort4*)g_Wl)[z * (DD * DD / 4) + r] = lv;
    }
}

// ---------------- QKV projection on wmma (round-14 known-good) ---------------
#define SMEM_QKV_BYTES ((2*128*QLDM + 2*64*QLDM) * 2)   // 55296

__global__ __launch_bounds__(256)
void qkv_wmma_kernel() {
    extern __shared__ __align__(128) unsigned char smq[];
    __nv_bfloat16* sXh = (__nv_bfloat16*)smq;
    __nv_bfloat16* sXl = sXh + 128 * QLDM;
    __nv_bfloat16* sWh = sXl + 128 * QLDM;
    __nv_bfloat16* sWl = sWh + 64 * QLDM;
    float* stage = (float*)smq;               // aliases sXh/sXl after k-loop

    int tid = threadIdx.x, wid = tid >> 5;
    int n0 = blockIdx.x * 128;
    int h  = blockIdx.y;
    int z  = blockIdx.z;
    int j0 = h * 64;

    const ushort4* Xh4 = (const ushort4*)g_Xh;   // row stride 64 ushort4
    const ushort4* Xl4 = (const ushort4*)g_Xl;
    const ushort4* Wh4 = (const ushort4*)g_Wh + (size_t)z * (DD * DD / 4);
    const ushort4* Wl4 = (const ushort4*)g_Wl + (size_t)z * (DD * DD / 4);

    int wm = wid & 3;       // 32-row block
    int wn = wid >> 2;      // 32-col block
    wmma::fragment<wmma::accumulator, 16, 16, 16, float> acc[2][2];
    #pragma unroll
    for (int i = 0; i < 2; i++)
        #pragma unroll
        for (int j = 0; j < 2; j++)
            wmma::fill_fragment(acc[i][j], 0.0f);

    for (int kt = 0; kt < 4; kt++) {
        __syncthreads();
        {   // X tile: 128 rows x 64 bf16 = 16 ushort4/row
            int r = tid >> 1, c0 = (tid & 1) * 8;
            #pragma unroll
            for (int c = 0; c < 8; c++) {
                *(ushort4*)(sXh + r * QLDM + (c0 + c) * 4) =
                    Xh4[(size_t)(n0 + r) * 64 + kt * 16 + c0 + c];
                *(ushort4*)(sXl + r * QLDM + (c0 + c) * 4) =
                    Xl4[(size_t)(n0 + r) * 64 + kt * 16 + c0 + c];
            }
        }
        {   // W tile: 64 rows (j) x 64 bf16; W row stride 64 ushort4
            int r = tid >> 2, c0 = (tid & 3) * 4;
            #pragma unroll
            for (int c = 0; c < 4; c++) {
                *(ushort4*)(sWh + r * QLDM + (c0 + c) * 4) =
                    Wh4[(size_t)(j0 + r) * 64 + kt * 16 + c0 + c];
                *(ushort4*)(sWl + r * QLDM + (c0 + c) * 4) =
                    Wl4[(size_t)(j0 + r) * 64 + kt * 16 + c0 + c];
            }
        }
        __syncthreads();

        #pragma unroll
        for (int ks = 0; ks < 4; ks++) {
            wmma::fragment<wmma::matrix_a, 16, 16, 16, __nv_bfloat16, wmma::row_major> ah[2], al[2];
            #pragma unroll
            for (int i = 0; i < 2; i++) {
                wmma::load_matrix_sync(ah[i], sXh + (wm * 32 + i * 16) * QLDM + ks * 16, QLDM);
                wmma::load_matrix_sync(al[i], sXl + (wm * 32 + i * 16) * QLDM + ks * 16, QLDM);
            }
            #pragma unroll
            for (int j = 0; j < 2; j++) {
                wmma::fragment<wmma::matrix_b, 16, 16, 16, __nv_bfloat16, wmma::col_major> bhf, blf;
                wmma::load_matrix_sync(bhf, sWh + (wn * 32 + j * 16) * QLDM + ks * 16, QLDM);
                wmma::load_matrix_sync(blf, sWl + (wn * 32 + j * 16) * QLDM + ks * 16, QLDM);
                #pragma unroll
                for (int i = 0; i < 2; i++) {
                    wmma::mma_sync(acc[i][j], ah[i], bhf, acc[i][j]);
                    wmma::mma_sync(acc[i][j], ah[i], blf, acc[i][j]);
                    wmma::mma_sync(acc[i][j], al[i], bhf, acc[i][j]);
                }
            }
        }
    }
    __syncthreads();   // done reading sX/sW; staging may alias

    #pragma unroll
    for (int i = 0; i < 2; i++)
        #pragma unroll
        for (int j = 0; j < 2; j++)
            wmma::store_matrix_sync(stage + (wm * 32 + i * 16) * 68 + wn * 32 + j * 16,
                                    acc[i][j], 68, wmma::mem_row_major);
    __syncthreads();

    // epilogue: thread -> row r = tid>>1, cols c0..c0+31
    {
        int r = tid >> 1, c0 = (tid & 1) * 32;
        int n = n0 + r;
        int bi = n >> 11, t = n & (TT - 1);
        size_t off = (((size_t)bi * HH + h) * TT + t) * HDIM + c0;
        float sc = (z == 0) ? 0.125f : 1.0f;
        #pragma unroll
        for (int c = 0; c < 8; c++) {
            float4 v = *(float4*)(stage + r * 68 + c0 + c * 4);
            if (z == 2) {
                *(float4*)(g_V + off + c * 4) = v;
            } else {
                v.x *= sc; v.y *= sc; v.z *= sc; v.w *= sc;
                ushort4 hv, lv;
                split4(v, hv, lv);
                unsigned short* H = (z == 0) ? g_Qh : g_Kh;
                unsigned short* L = (z == 0) ? g_Ql : g_Kl;
                *(ushort4*)(H + off + c * 4) = hv;
                *(ushort4*)(L + off + c * 4) = lv;
            }
        }
    }
}

// ---------------- score GEMM on wmma/HMMA, cp.async double-buffered K -------
// smem (bf16 elems): sQh @0, sQl @128*QLDM, K buffers: buf b hi @(2+2b),
// lo @(3+2b) * 128*QLDM. Total 6*128*QLDM*2 = 110592 B.
#define SMEM_WMMA_BYTES (6 * 128 * QLDM * 2)

__global__ __launch_bounds__(256)
void score_wmma_kernel() {
    extern __shared__ __align__(128) __nv_bfloat16 sm[];
    __nv_bfloat16* sQh = sm;
    __nv_bfloat16* sQl = sm + 128 * QLDM;
    uint32_t sb32 = smem_u32(sm);

    int tid = threadIdx.x, wid = tid >> 5;
    int qt = blockIdx.x, h = blockIdx.y, b = blockIdx.z;
    size_t bh = (size_t)b * HH + h;

    const ushort4* Qhg = (const ushort4*)(g_Qh + (bh * TT + (size_t)qt * 128) * HDIM);
    const ushort4* Qlg = (const ushort4*)(g_Ql + (bh * TT + (size_t)qt * 128) * HDIM);
    const uint4* Khg4 = (const uint4*)(g_Kh + bh * TT * HDIM);   // row = 8 x uint4
    const uint4* Klg4 = (const uint4*)(g_Kl + bh * TT * HDIM);

    // ---- load Q tile hi/lo: 128 rows x 64 bf16 (16 ushort4/row) ----
    {
        int r = tid >> 1, c0 = (tid & 1) * 8;
        #pragma unroll
        for (int c = 0; c < 8; c++) {
            *(ushort4*)(sQh + r * QLDM + (c0 + c) * 4) = Qhg[r * 16 + c0 + c];
            *(ushort4*)(sQl + r * QLDM + (c0 + c) * 4) = Qlg[r * 16 + c0 + c];
        }
    }

    // ---- async K tile loader: 128 rows x 128 B (hi) + 128 B (lo) ----
    int lr = tid >> 1, lc0 = (tid & 1) * 4;       // 4 x 16B chunks each
    auto loadK = [&](int kt, int bi) {
        const uint4* kh = Khg4 + ((size_t)kt * 128 + lr) * 8 + lc0;
        const uint4* kl = Klg4 + ((size_t)kt * 128 + lr) * 8 + lc0;
        uint32_t dh = sb32 + ((2 + 2 * bi) * 128 * QLDM + lr * QLDM) * 2 + lc0 * 16;
        uint32_t dl = sb32 + ((3 + 2 * bi) * 128 * QLDM + lr * QLDM) * 2 + lc0 * 16;
        #pragma unroll
        for (int c = 0; c < 4; c++) {
            cp_async16(dh + c * 16, kh + c);
            cp_async16(dl + c * 16, kl + c);
        }
    };

    loadK(0, 0); CP_COMMIT();
    loadK(1, 1); CP_COMMIT();

    int wm = wid & 3;      // 32-query block within tile
    int wn = wid >> 2;     // 64-key block within tile
    float* Sbase = g_S + (bh * TT + (size_t)qt * 128) * TT;

    for (int kt = 0; kt < 16; kt++) {
        int bi = kt & 1;
        __nv_bfloat16* sKh = sm + (2 + 2 * bi) * 128 * QLDM;
        __nv_bfloat16* sKl = sm + (3 + 2 * bi) * 128 * QLDM;
        CP_WAIT1();            // tile kt's group complete
        __syncthreads();

        wmma::fragment<wmma::accumulator, 16, 16, 16, float> acc[2][4];
        #pragma unroll
        for (int i = 0; i < 2; i++)
            #pragma unroll
            for (int j = 0; j < 4; j++)
                wmma::fill_fragment(acc[i][j], 0.0f);

        #pragma unroll
        for (int ks = 0; ks < 4; ks++) {
            wmma::fragment<wmma::matrix_a, 16, 16, 16, __nv_bfloat16, wmma::row_major> ah[2], al[2];
            #pragma unroll
            for (int i = 0; i < 2; i++) {
                wmma::load_matrix_sync(ah[i], sQh + (wm * 32 + i * 16) * QLDM + ks * 16, QLDM);
                wmma::load_matrix_sync(al[i], sQl + (wm * 32 + i * 16) * QLDM + ks * 16, QLDM);
            }
            #pragma unroll
            for (int j = 0; j < 4; j++) {
                wmma::fragment<wmma::matrix_b, 16, 16, 16, __nv_bfloat16, wmma::col_major> bhf, blf;
                wmma::load_matrix_sync(bhf, sKh + (wn * 64 + j * 16) * QLDM + ks * 16, QLDM);
                wmma::load_matrix_sync(blf, sKl + (wn * 64 + j * 16) * QLDM + ks * 16, QLDM);
                #pragma unroll
                for (int i = 0; i < 2; i++) {
                    wmma::mma_sync(acc[i][j], ah[i], bhf, acc[i][j]);
                    wmma::mma_sync(acc[i][j], ah[i], blf, acc[i][j]);
                    wmma::mma_sync(acc[i][j], al[i], bhf, acc[i][j]);
                }
            }
        }
        #pragma unroll
        for (int i = 0; i < 2; i++)
            #pragma unroll
            for (int j = 0; j < 4; j++)
                wmma::store_matrix_sync(
                    Sbase + (size_t)(wm * 32 + i * 16) * TT + kt * 128 + wn * 64 + j * 16,
                    acc[i][j], TT, wmma::mem_row_major);

        __syncthreads();       // all warps done reading buffer bi
        if (kt + 2 < 16) { loadK(kt + 2, bi); CP_COMMIT(); }
    }
}

// ---------------- sparsemax + sparse AV (round-10, unchanged) ---------------
__global__ __launch_bounds__(256)
void spmax_av_kernel() {
    __shared__ float sVal[8 * CAND_CAP];           // 16 KB
    __shared__ unsigned short sKey[8 * CAND_CAP];  // 8 KB
    int wid = threadIdx.x >> 5, lane = threadIdx.x & 31;
    int rid = blockIdx.x * 8 + wid;               // [0, NROWS)
    int b = rid >> 13, h = (rid >> 11) & 3, q = rid & 2047;

    const float4* Srow = (const float4*)(g_S + (size_t)rid * TT);
    const uchar4* pad4 = (const uchar4*)(g_pad + b * TT);

    float z[64];
    float zmax = -3e38f;
    #pragma unroll
    for (int it = 0; it < 16; it++) {
        float4 sv = Srow[it * 32 + lane];
        uchar4 p = pad4[it * 32 + lane];
        float z0 = p.x ? NEGV : sv.x;
        float z1 = p.y ? NEGV : sv.y;
        float z2 = p.z ? NEGV : sv.z;
        float z3 = p.w ? NEGV : sv.w;
        z[it * 4 + 0] = z0; z[it * 4 + 1] = z1;
        z[it * 4 + 2] = z2; z[it * 4 + 3] = z3;
        zmax = fmaxf(fmaxf(fmaxf(zmax, z0), fmaxf(z1, z2)), z3);
    }
    #pragma unroll
    for (int o = 16; o; o >>= 1) zmax = fmaxf(zmax, __shfl_xor_sync(0xffffffffu, zmax, o));

    float tau = zmax - 1.0f;
    #pragma unroll 1
    for (int it = 0; it < 5; it++) {
        float s = 0.f, c = 0.f;
        #pragma unroll
        for (int i = 0; i < 64; i++) {
            if (z[i] > tau) { s += z[i]; c += 1.0f; }
        }
        #pragma unroll
        for (int o = 16; o; o >>= 1) {
            s += __shfl_xor_sync(0xffffffffu, s, o);
            c += __shfl_xor_sync(0xffffffffu, c, o);
        }
        float nt = (s - 1.0f) / c;
        if (nt == tau) break;
        tau = nt;
    }

    int base = wid * CAND_CAP;
    unsigned cnt = 0;
    #pragma unroll
    for (int i = 0; i < 64; i++) {
        bool cand = z[i] > tau;
        unsigned m = __ballot_sync(0xffffffffu, cand);
        if (cand) {
            int pos = cnt + __popc(m & ((1u << lane) - 1u));
            if (pos < CAND_CAP) {
                sVal[base + pos] = z[i];
                sKey[base + pos] = (unsigned short)(((i >> 2) << 7) + (lane << 2) + (i & 3));
            }
        }
        cnt += __popc(m);
    }
    __syncwarp();

    const float* Vb = g_V + ((size_t)(b * HH + h) * TT) * HDIM;
    float2 acc = make_float2(0.f, 0.f);

    if (cnt <= CAND_CAP) {
        int n = (int)cnt;
        #pragma unroll 1
        for (int it = 0; it < 27; it++) {
            float s = 0.f, c = 0.f;
            for (int j = lane; j < n; j += 32) {
                float v = sVal[base + j];
                if (v > tau) { s += v; c += 1.0f; }
            }
            #pragma unroll
            for (int o = 16; o; o >>= 1) {
                s += __shfl_xor_sync(0xffffffffu, s, o);
                c += __shfl_xor_sync(0xffffffffu, c, o);
            }
            float nt = (s - 1.0f) / c;
            if (nt == tau) break;
            tau = nt;
        }
        for (int j = 0; j < n; j++) {
            float w = sVal[base + j] - tau;
            if (w > 0.f) {
                int k = sKey[base + j];
                float2 vv = *(const float2*)&Vb[(size_t)k * HDIM + lane * 2];
                acc.x += w * vv.x;
                acc.y += w * vv.y;
            }
        }
    } else {
        #pragma unroll 1
        for (int it = 0; it < 27; it++) {
            float s = 0.f, c = 0.f;
            #pragma unroll
            for (int i = 0; i < 64; i++) {
                if (z[i] > tau) { s += z[i]; c += 1.0f; }
            }
            #pragma unroll
            for (int o = 16; o; o >>= 1) {
                s += __shfl_xor_sync(0xffffffffu, s, o);
                c += __shfl_xor_sync(0xffffffffu, c, o);
            }
            float nt = (s - 1.0f) / c;
            if (nt == tau) break;
            tau = nt;
        }
        #pragma unroll
        for (int g = 0; g < 16; g++) {
            #pragma unroll
            for (int j = 0; j < 4; j++) {
                float zz = z[g * 4 + j];
                unsigned m = __ballot_sync(0xffffffffu, zz > tau);
                while (m) {
                    int src = __ffs(m) - 1;
                    m &= m - 1;
                    float w = __shfl_sync(0xffffffffu, zz, src) - tau;
                    int k = g * 128 + src * 4 + j;
                    float2 v = *(const float2*)&Vb[(size_t)k * HDIM + lane * 2];
                    acc.x += w * v.x;
                    acc.y += w * v.y;
                }
            }
        }
    }
    *(float2*)&g_attn[((size_t)b * TT + q) * DD + h * HDIM + lane * 2] = acc;
}

// ---------------- out-proj + residual + LayerNorm (known-good) --------------
__global__ __launch_bounds__(256)
void outproj_ln_kernel(const float* __restrict__ x,
                       const float* __restrict__ Wo,
                       const float* __restrict__ gamma,
                       const float* __restrict__ beta,
                       float* __restrict__ out) {
    __shared__ float sA[16][DD];
    __shared__ float sY[16][DD + 1];
    __shared__ float sMu[16], sRs[16];
    int n0 = blockIdx.x * 16;
    int tid = threadIdx.x;              // output column j

    for (int i = tid; i < 16 * 64; i += 256) {
        int r = i >> 6, c4 = (i & 63) * 4;
        *(float4*)&sA[r][c4] = *(const float4*)&g_attn[((size_t)n0 + r) * DD + c4];
    }
    __syncthreads();

    unsigned long long acc2[16] = {};
    const ulonglong2* wrow = (const ulonglong2*)(Wo + (size_t)tid * DD);
    #pragma unroll 4
    for (int c = 0; c < 64; c++) {
        ulonglong2 w = wrow[c];
        #pragma unroll
        for (int r = 0; r < 16; r++) {
            ulonglong2 a = *(const ulonglong2*)&sA[r][c * 4];
            ffma2(acc2[r], w.x, a.x);
            ffma2(acc2[r], w.y, a.y);
        }
    }
    #pragma unroll
    for (int r = 0; r < 16; r++)
        sY[r][tid] = hsum2(acc2[r]) + x[((size_t)n0 + r) * DD + tid];
    __syncthreads();

    int wid = tid >> 5, lane = tid & 31;
    for (int rr = 0; rr < 2; rr++) {
        int r = wid * 2 + rr;
        float s = 0.f, s2 = 0.f;
        #pragma unroll
        for (int i = 0; i < 8; i++) {
            float v = sY[r][lane * 8 + i];
            s += v; s2 += v * v;
        }
        #pragma unroll
        for (int o = 16; o; o >>= 1) {
            s  += __shfl_xor_sync(0xffffffffu, s, o);
            s2 += __shfl_xor_sync(0xffffffffu, s2, o);
        }
        if (lane == 0) {
            float mu = s * (1.0f / DD);
            sMu[r] = mu;
            sRs[r] = rsqrtf(s2 * (1.0f / DD) - mu * mu + EPSV);
        }
    }
    __syncthreads();
    float g = gamma[tid], bt = beta[tid];
    #pragma unroll
    for (int r = 0; r < 16; r++)
        out[((size_t)n0 + r) * DD + tid] = (sY[r][tid] - sMu[r]) * sRs[r] * g + bt;
}

// ---------------- launch ----------------------------------------------------
extern "C" void kernel_launch(void* const* d_in, const int* in_sizes, int n_in,
                              void* d_out, int out_size) {
    const float* x     = (const float*)d_in[0];
    const void*  mask  = d_in[1];
    const float* Wq    = (const float*)d_in[2];
    const float* Wk    = (const float*)d_in[3];
    const float* Wv    = (const float*)d_in[4];
    const float* Wo    = (const float*)d_in[5];
    const float* gamma = (const float*)d_in[6];
    const float* beta  = (const float*)d_in[7];
    float* out = (float*)d_out;

    cudaFuncSetAttribute(score_wmma_kernel,
                         cudaFuncAttributeMaxDynamicSharedMemorySize, SMEM_WMMA_BYTES);
    cudaFuncSetAttribute(qkv_wmma_kernel,
                         cudaFuncAttributeMaxDynamicSharedMemorySize, SMEM_QKV_BYTES);

    mask_prep_kernel<<<1, 256>>>(mask);
    decompose_kernel<<<(NX4 + NW4 + 255) / 256, 256>>>(x, Wq, Wk, Wv);
    qkv_wmma_kernel<<<dim3(NT / 128, HH, 3), 256, SMEM_QKV_BYTES>>>();
    score_wmma_kernel<<<dim3(16, HH, BB), 256, SMEM_WMMA_BYTES>>>();
    spmax_av_kernel<<<NROWS / 8, 256>>>();
    outproj_ln_kernel<<<NT / 16, 256>>>(x, Wo, gamma, beta, out);
}

// round 16
// speedup vs baseline: 3.6302x; 1.0650x over previous
#include <cuda_runtime.h>
#include <cuda_bf16.h>
#include <mma.h>
#include <cstdint>

using namespace nvcuda;

#define BB 8
#define TT 2048
#define DD 256
#define HH 4
#define HDIM 64
#define NT (BB*TT)           // 16384 rows
#define NROWS (BB*HH*TT)     // 65536 attention score rows
#define NEGV (-1e9f)
#define EPSV 1e-5f
#define CAND_CAP 512
#define QLDM 72              // bf16 smem leading dim (mult of 8; 144 B row)
#define WLDM 40              // bf16 smem ldm for 32-wide k tiles
#define SLD 260              // fp32 staging ldm in outproj

// ---------------- device scratch (module-load allocated) --------------------
__device__ unsigned short g_Xh[NT*DD];           // bf16 hi of x
__device__ unsigned short g_Xl[NT*DD];           // bf16 lo of x
__device__ unsigned short g_Wh[3*DD*DD];         // bf16 hi of Wq,Wk,Wv
__device__ unsigned short g_Wl[3*DD*DD];         // bf16 lo
__device__ unsigned short g_WoH[DD*DD];          // bf16 hi of Wo
__device__ unsigned short g_WoL[DD*DD];          // bf16 lo of Wo
__device__ unsigned short g_Qh[BB*HH*TT*HDIM];   // bf16 hi of Q/8
__device__ unsigned short g_Ql[BB*HH*TT*HDIM];   // bf16 lo of Q/8
__device__ unsigned short g_Kh[BB*HH*TT*HDIM];   // bf16 hi of K
__device__ unsigned short g_Kl[BB*HH*TT*HDIM];   // bf16 lo of K
__device__ float g_V[BB*HH*TT*HDIM];
__device__ float g_S[(size_t)BB*HH*TT*TT];       // 512 MiB score scratch
__device__ unsigned short g_attnH[NT*DD];        // bf16 hi of attn out
__device__ unsigned short g_attnL[NT*DD];        // bf16 lo
__device__ unsigned char g_pad[NT];

// ---------------- packed fp32x2 helpers -------------------------------------
union F2U { unsigned long long u; float2 f; };

__device__ __forceinline__ float hsum2(unsigned long long u) {
    F2U t; t.u = u; return t.f.x + t.f.y;
}

// hi/lo bf16 split of a float4
__device__ __forceinline__ void split4(float4 v, ushort4& hv, ushort4& lv) {
    __nv_bfloat16 h0 = __float2bfloat16(v.x), h1 = __float2bfloat16(v.y);
    __nv_bfloat16 h2 = __float2bfloat16(v.z), h3 = __float2bfloat16(v.w);
    __nv_bfloat16 l0 = __float2bfloat16(v.x - __bfloat162float(h0));
    __nv_bfloat16 l1 = __float2bfloat16(v.y - __bfloat162float(h1));
    __nv_bfloat16 l2 = __float2bfloat16(v.z - __bfloat162float(h2));
    __nv_bfloat16 l3 = __float2bfloat16(v.w - __bfloat162float(h3));
    hv = make_ushort4(__bfloat16_as_ushort(h0), __bfloat16_as_ushort(h1),
                      __bfloat16_as_ushort(h2), __bfloat16_as_ushort(h3));
    lv = make_ushort4(__bfloat16_as_ushort(l0), __bfloat16_as_ushort(l1),
                      __bfloat16_as_ushort(l2), __bfloat16_as_ushort(l3));
}

__device__ __forceinline__ uint32_t smem_u32(const void* p) {
    uint32_t a;
    asm("{ .reg .u64 t; cvta.to.shared.u64 t, %1; cvt.u32.u64 %0, t; }"
        : "=r"(a) : "l"(p));
    return a;
}
__device__ __forceinline__ void cp_async16(uint32_t dst, const void* src) {
    asm volatile("cp.async.cg.shared.global [%0], [%1], 16;"
                 :: "r"(dst), "l"(src));
}
#define CP_COMMIT() asm volatile("cp.async.commit_group;" ::: "memory")
#define CP_WAIT1()  asm volatile("cp.async.wait_group 1;" ::: "memory")

// ---------------- mask dtype detection + expansion --------------------------
__global__ void mask_prep_kernel(const void* __restrict__ maskraw) {
    __shared__ int cntOff, cnt3F, mode;
    const unsigned char* b = (const unsigned char*)maskraw;
    int tid = threadIdx.x;
    if (tid == 0) { cntOff = 0; cnt3F = 0; }
    __syncthreads();
    int lo = 0, l3 = 0;
    for (int i = tid; i < NT; i += blockDim.x) {
        unsigned char v = b[i];
        if ((i & 3) != 0 && v != 0) lo++;
        if ((i & 3) == 3 && v == 0x3F) l3++;
    }
    atomicAdd(&cntOff, lo);
    atomicAdd(&cnt3F, l3);
    __syncthreads();
    if (tid == 0) {
        if (cnt3F > 0) mode = 2;            // float32
        else if (cntOff > 0) mode = 0;      // uint8 / bool
        else mode = 1;                      // int32
    }
    __syncthreads();
    int m = mode;
    for (int i = tid; i < NT; i += blockDim.x) {
        unsigned char p;
        if (m == 0)      p = (b[i] != 0);
        else if (m == 1) p = (((const int*)maskraw)[i] != 0);
        else             p = (((const float*)maskraw)[i] != 0.0f);
        g_pad[i] = p;
    }
}

// ---------------- decompose x, Wq/Wk/Wv, Wo into bf16 hi/lo ------------------
#define NX4 (NT*DD/4)        // 1048576 float4 of x
#define NW4 (3*DD*DD/4)      // 49152 float4 of Wq/Wk/Wv
#define NWO4 (DD*DD/4)       // 16384 float4 of Wo
__global__ __launch_bounds__(256)
void decompose_kernel(const float* __restrict__ x,
                      const float* __restrict__ Wq,
                      const float* __restrict__ Wk,
                      const float* __restrict__ Wv,
                      const float* __restrict__ Wo) {
    int idx = blockIdx.x * 256 + threadIdx.x;
    if (idx < NX4) {
        float4 v = ((const float4*)x)[idx];
        ushort4 hv, lv;
        split4(v, hv, lv);
        ((ushort4*)g_Xh)[idx] = hv;
        ((ushort4*)g_Xl)[idx] = lv;
    } else if (idx < NX4 + NW4) {
        int w = idx - NX4;
        int z = w / (DD * DD / 4), r = w % (DD * DD / 4);
        const float* W = (z == 0) ? Wq : (z == 1 ? Wk : Wv);
        float4 v = ((const float4*)W)[r];
        ushort4 hv, lv;
        split4(v, hv, lv);
        ((ushort4*)g_Wh)[z * (DD * DD / 4) + r] = hv;
        ((ushort4*)g_Wl)[z * (DD * DD / 4) + r] = lv;
    } else if (idx < NX4 + NW4 + NWO4) {
        int r = idx - NX4 - NW4;
        float4 v = ((const float4*)Wo)[r];
        ushort4 hv, lv;
        split4(v, hv, lv);
        ((ushort4*)g_WoH)[r] = hv;
        ((ushort4*)g_WoL)[r] = lv;
    }
}

// ---------------- QKV projection on wmma (round-14 known-good) ---------------
#define SMEM_QKV_BYTES ((2*128*QLDM + 2*64*QLDM) * 2)   // 55296

__global__ __launch_bounds__(256)
void qkv_wmma_kernel() {
    extern __shared__ __align__(128) unsigned char smq[];
    __nv_bfloat16* sXh = (__nv_bfloat16*)smq;
    __nv_bfloat16* sXl = sXh + 128 * QLDM;
    __nv_bfloat16* sWh = sXl + 128 * QLDM;
    __nv_bfloat16* sWl = sWh + 64 * QLDM;
    float* stage = (float*)smq;               // aliases sXh/sXl after k-loop

    int tid = threadIdx.x, wid = tid >> 5;
    int n0 = blockIdx.x * 128;
    int h  = blockIdx.y;
    int z  = blockIdx.z;
    int j0 = h * 64;

    const ushort4* Xh4 = (const ushort4*)g_Xh;   // row stride 64 ushort4
    const ushort4* Xl4 = (const ushort4*)g_Xl;
    const ushort4* Wh4 = (const ushort4*)g_Wh + (size_t)z * (DD * DD / 4);
    const ushort4* Wl4 = (const ushort4*)g_Wl + (size_t)z * (DD * DD / 4);

    int wm = wid & 3;       // 32-row block
    int wn = wid >> 2;      // 32-col block
    wmma::fragment<wmma::accumulator, 16, 16, 16, float> acc[2][2];
    #pragma unroll
    for (int i = 0; i < 2; i++)
        #pragma unroll
        for (int j = 0; j < 2; j++)
            wmma::fill_fragment(acc[i][j], 0.0f);

    for (int kt = 0; kt < 4; kt++) {
        __syncthreads();
        {   // X tile: 128 rows x 64 bf16 = 16 ushort4/row
            int r = tid >> 1, c0 = (tid & 1) * 8;
            #pragma unroll
            for (int c = 0; c < 8; c++) {
                *(ushort4*)(sXh + r * QLDM + (c0 + c) * 4) =
                    Xh4[(size_t)(n0 + r) * 64 + kt * 16 + c0 + c];
                *(ushort4*)(sXl + r * QLDM + (c0 + c) * 4) =
                    Xl4[(size_t)(n0 + r) * 64 + kt * 16 + c0 + c];
            }
        }
        {   // W tile: 64 rows (j) x 64 bf16; W row stride 64 ushort4
            int r = tid >> 2, c0 = (tid & 3) * 4;
            #pragma unroll
            for (int c = 0; c < 4; c++) {
                *(ushort4*)(sWh + r * QLDM + (c0 + c) * 4) =
                    Wh4[(size_t)(j0 + r) * 64 + kt * 16 + c0 + c];
                *(ushort4*)(sWl + r * QLDM + (c0 + c) * 4) =
                    Wl4[(size_t)(j0 + r) * 64 + kt * 16 + c0 + c];
            }
        }
        __syncthreads();

        #pragma unroll
        for (int ks = 0; ks < 4; ks++) {
            wmma::fragment<wmma::matrix_a, 16, 16, 16, __nv_bfloat16, wmma::row_major> ah[2], al[2];
            #pragma unroll
            for (int i = 0; i < 2; i++) {
                wmma::load_matrix_sync(ah[i], sXh + (wm * 32 + i * 16) * QLDM + ks * 16, QLDM);
                wmma::load_matrix_sync(al[i], sXl + (wm * 32 + i * 16) * QLDM + ks * 16, QLDM);
            }
            #pragma unroll
            for (int j = 0; j < 2; j++) {
                wmma::fragment<wmma::matrix_b, 16, 16, 16, __nv_bfloat16, wmma::col_major> bhf, blf;
                wmma::load_matrix_sync(bhf, sWh + (wn * 32 + j * 16) * QLDM + ks * 16, QLDM);
                wmma::load_matrix_sync(blf, sWl + (wn * 32 + j * 16) * QLDM + ks * 16, QLDM);
                #pragma unroll
                for (int i = 0; i < 2; i++) {
                    wmma::mma_sync(acc[i][j], ah[i], bhf, acc[i][j]);
                    wmma::mma_sync(acc[i][j], ah[i], blf, acc[i][j]);
                    wmma::mma_sync(acc[i][j], al[i], bhf, acc[i][j]);
                }
            }
        }
    }
    __syncthreads();   // done reading sX/sW; staging may alias

    #pragma unroll
    for (int i = 0; i < 2; i++)
        #pragma unroll
        for (int j = 0; j < 2; j++)
            wmma::store_matrix_sync(stage + (wm * 32 + i * 16) * 68 + wn * 32 + j * 16,
                                    acc[i][j], 68, wmma::mem_row_major);
    __syncthreads();

    // epilogue: thread -> row r = tid>>1, cols c0..c0+31
    {
        int r = tid >> 1, c0 = (tid & 1) * 32;
        int n = n0 + r;
        int bi = n >> 11, t = n & (TT - 1);
        size_t off = (((size_t)bi * HH + h) * TT + t) * HDIM + c0;
        float sc = (z == 0) ? 0.125f : 1.0f;
        #pragma unroll
        for (int c = 0; c < 8; c++) {
            float4 v = *(float4*)(stage + r * 68 + c0 + c * 4);
            if (z == 2) {
                *(float4*)(g_V + off + c * 4) = v;
            } else {
                v.x *= sc; v.y *= sc; v.z *= sc; v.w *= sc;
                ushort4 hv, lv;
                split4(v, hv, lv);
                unsigned short* H = (z == 0) ? g_Qh : g_Kh;
                unsigned short* L = (z == 0) ? g_Ql : g_Kl;
                *(ushort4*)(H + off + c * 4) = hv;
                *(ushort4*)(L + off + c * 4) = lv;
            }
        }
    }
}

// ---------------- score GEMM on wmma/HMMA, cp.async double-buffered K -------
#define SMEM_WMMA_BYTES (6 * 128 * QLDM * 2)

__global__ __launch_bounds__(256)
void score_wmma_kernel() {
    extern __shared__ __align__(128) __nv_bfloat16 sm[];
    __nv_bfloat16* sQh = sm;
    __nv_bfloat16* sQl = sm + 128 * QLDM;
    uint32_t sb32 = smem_u32(sm);

    int tid = threadIdx.x, wid = tid >> 5;
    int qt = blockIdx.x, h = blockIdx.y, b = blockIdx.z;
    size_t bh = (size_t)b * HH + h;

    const ushort4* Qhg = (const ushort4*)(g_Qh + (bh * TT + (size_t)qt * 128) * HDIM);
    const ushort4* Qlg = (const ushort4*)(g_Ql + (bh * TT + (size_t)qt * 128) * HDIM);
    const uint4* Khg4 = (const uint4*)(g_Kh + bh * TT * HDIM);   // row = 8 x uint4
    const uint4* Klg4 = (const uint4*)(g_Kl + bh * TT * HDIM);

    {
        int r = tid >> 1, c0 = (tid & 1) * 8;
        #pragma unroll
        for (int c = 0; c < 8; c++) {
            *(ushort4*)(sQh + r * QLDM + (c0 + c) * 4) = Qhg[r * 16 + c0 + c];
            *(ushort4*)(sQl + r * QLDM + (c0 + c) * 4) = Qlg[r * 16 + c0 + c];
        }
    }

    int lr = tid >> 1, lc0 = (tid & 1) * 4;       // 4 x 16B chunks each
    auto loadK = [&](int kt, int bi) {
        const uint4* kh = Khg4 + ((size_t)kt * 128 + lr) * 8 + lc0;
        const uint4* kl = Klg4 + ((size_t)kt * 128 + lr) * 8 + lc0;
        uint32_t dh = sb32 + ((2 + 2 * bi) * 128 * QLDM + lr * QLDM) * 2 + lc0 * 16;
        uint32_t dl = sb32 + ((3 + 2 * bi) * 128 * QLDM + lr * QLDM) * 2 + lc0 * 16;
        #pragma unroll
        for (int c = 0; c < 4; c++) {
            cp_async16(dh + c * 16, kh + c);
            cp_async16(dl + c * 16, kl + c);
        }
    };

    loadK(0, 0); CP_COMMIT();
    loadK(1, 1); CP_COMMIT();

    int wm = wid & 3;      // 32-query block within tile
    int wn = wid >> 2;     // 64-key block within tile
    float* Sbase = g_S + (bh * TT + (size_t)qt * 128) * TT;

    for (int kt = 0; kt < 16; kt++) {
        int bi = kt & 1;
        __nv_bfloat16* sKh = sm + (2 + 2 * bi) * 128 * QLDM;
        __nv_bfloat16* sKl = sm + (3 + 2 * bi) * 128 * QLDM;
        CP_WAIT1();
        __syncthreads();

        wmma::fragment<wmma::accumulator, 16, 16, 16, float> acc[2][4];
        #pragma unroll
        for (int i = 0; i < 2; i++)
            #pragma unroll
            for (int j = 0; j < 4; j++)
                wmma::fill_fragment(acc[i][j], 0.0f);

        #pragma unroll
        for (int ks = 0; ks < 4; ks++) {
            wmma::fragment<wmma::matrix_a, 16, 16, 16, __nv_bfloat16, wmma::row_major> ah[2], al[2];
            #pragma unroll
            for (int i = 0; i < 2; i++) {
                wmma::load_matrix_sync(ah[i], sQh + (wm * 32 + i * 16) * QLDM + ks * 16, QLDM);
                wmma::load_matrix_sync(al[i], sQl + (wm * 32 + i * 16) * QLDM + ks * 16, QLDM);
            }
            #pragma unroll
            for (int j = 0; j < 4; j++) {
                wmma::fragment<wmma::matrix_b, 16, 16, 16, __nv_bfloat16, wmma::col_major> bhf, blf;
                wmma::load_matrix_sync(bhf, sKh + (wn * 64 + j * 16) * QLDM + ks * 16, QLDM);
                wmma::load_matrix_sync(blf, sKl + (wn * 64 + j * 16) * QLDM + ks * 16, QLDM);
                #pragma unroll
                for (int i = 0; i < 2; i++) {
                    wmma::mma_sync(acc[i][j], ah[i], bhf, acc[i][j]);
                    wmma::mma_sync(acc[i][j], ah[i], blf, acc[i][j]);
                    wmma::mma_sync(acc[i][j], al[i], bhf, acc[i][j]);
                }
            }
        }
        #pragma unroll
        for (int i = 0; i < 2; i++)
            #pragma unroll
            for (int j = 0; j < 4; j++)
                wmma::store_matrix_sync(
                    Sbase + (size_t)(wm * 32 + i * 16) * TT + kt * 128 + wn * 64 + j * 16,
                    acc[i][j], TT, wmma::mem_row_major);

        __syncthreads();
        if (kt + 2 < 16) { loadK(kt + 2, bi); CP_COMMIT(); }
    }
}

// ---------------- sparsemax + sparse AV: emits attn as bf16 hi/lo -----------
__global__ __launch_bounds__(256)
void spmax_av_kernel() {
    __shared__ float sVal[8 * CAND_CAP];           // 16 KB
    __shared__ unsigned short sKey[8 * CAND_CAP];  // 8 KB
    int wid = threadIdx.x >> 5, lane = threadIdx.x & 31;
    int rid = blockIdx.x * 8 + wid;               // [0, NROWS)
    int b = rid >> 13, h = (rid >> 11) & 3, q = rid & 2047;

    const float4* Srow = (const float4*)(g_S + (size_t)rid * TT);
    const uchar4* pad4 = (const uchar4*)(g_pad + b * TT);

    float z[64];
    float zmax = -3e38f;
    #pragma unroll
    for (int it = 0; it < 16; it++) {
        float4 sv = Srow[it * 32 + lane];
        uchar4 p = pad4[it * 32 + lane];
        float z0 = p.x ? NEGV : sv.x;
        float z1 = p.y ? NEGV : sv.y;
        float z2 = p.z ? NEGV : sv.z;
        float z3 = p.w ? NEGV : sv.w;
        z[it * 4 + 0] = z0; z[it * 4 + 1] = z1;
        z[it * 4 + 2] = z2; z[it * 4 + 3] = z3;
        zmax = fmaxf(fmaxf(fmaxf(zmax, z0), fmaxf(z1, z2)), z3);
    }
    #pragma unroll
    for (int o = 16; o; o >>= 1) zmax = fmaxf(zmax, __shfl_xor_sync(0xffffffffu, zmax, o));

    float tau = zmax - 1.0f;
    #pragma unroll 1
    for (int it = 0; it < 5; it++) {
        float s = 0.f, c = 0.f;
        #pragma unroll
        for (int i = 0; i < 64; i++) {
            if (z[i] > tau) { s += z[i]; c += 1.0f; }
        }
        #pragma unroll
        for (int o = 16; o; o >>= 1) {
            s += __shfl_xor_sync(0xffffffffu, s, o);
            c += __shfl_xor_sync(0xffffffffu, c, o);
        }
        float nt = (s - 1.0f) / c;
        if (nt == tau) break;
        tau = nt;
    }

    int base = wid * CAND_CAP;
    unsigned cnt = 0;
    #pragma unroll
    for (int i = 0; i < 64; i++) {
        bool cand = z[i] > tau;
        unsigned m = __ballot_sync(0xffffffffu, cand);
        if (cand) {
            int pos = cnt + __popc(m & ((1u << lane) - 1u));
            if (pos < CAND_CAP) {
                sVal[base + pos] = z[i];
                sKey[base + pos] = (unsigned short)(((i >> 2) << 7) + (lane << 2) + (i & 3));
            }
        }
        cnt += __popc(m);
    }
    __syncwarp();

    const float* Vb = g_V + ((size_t)(b * HH + h) * TT) * HDIM;
    float2 acc = make_float2(0.f, 0.f);

    if (cnt <= CAND_CAP) {
        int n = (int)cnt;
        #pragma unroll 1
        for (int it = 0; it < 27; it++) {
            float s = 0.f, c = 0.f;
            for (int j = lane; j < n; j += 32) {
                float v = sVal[base + j];
                if (v > tau) { s += v; c += 1.0f; }
            }
            #pragma unroll
            for (int o = 16; o; o >>= 1) {
                s += __shfl_xor_sync(0xffffffffu, s, o);
                c += __shfl_xor_sync(0xffffffffu, c, o);
            }
            float nt = (s - 1.0f) / c;
            if (nt == tau) break;
            tau = nt;
        }
        for (int j = 0; j < n; j++) {
            float w = sVal[base + j] - tau;
            if (w > 0.f) {
                int k = sKey[base + j];
                float2 vv = *(const float2*)&Vb[(size_t)k * HDIM + lane * 2];
                acc.x += w * vv.x;
                acc.y += w * vv.y;
            }
        }
    } else {
        #pragma unroll 1
        for (int it = 0; it < 27; it++) {
            float s = 0.f, c = 0.f;
            #pragma unroll
            for (int i = 0; i < 64; i++) {
                if (z[i] > tau) { s += z[i]; c += 1.0f; }
            }
            #pragma unroll
            for (int o = 16; o; o >>= 1) {
                s += __shfl_xor_sync(0xffffffffu, s, o);
                c += __shfl_xor_sync(0xffffffffu, c, o);
            }
            float nt = (s - 1.0f) / c;
            if (nt == tau) break;
            tau = nt;
        }
        #pragma unroll
        for (int g = 0; g < 16; g++) {
            #pragma unroll
            for (int j = 0; j < 4; j++) {
                float zz = z[g * 4 + j];
                unsigned m = __ballot_sync(0xffffffffu, zz > tau);
                while (m) {
                    int src = __ffs(m) - 1;
                    m &= m - 1;
                    float w = __shfl_sync(0xffffffffu, zz, src) - tau;
                    int k = g * 128 + src * 4 + j;
                    float2 v = *(const float2*)&Vb[(size_t)k * HDIM + lane * 2];
                    acc.x += w * v.x;
                    acc.y += w * v.y;
                }
            }
        }
    }
    // emit attn as bf16 hi/lo (fp32 values split; outproj reconstructs)
    {
        size_t off = ((size_t)b * TT + q) * DD + h * HDIM + lane * 2;
        __nv_bfloat16 h0 = __float2bfloat16(acc.x);
        __nv_bfloat16 h1 = __float2bfloat16(acc.y);
        __nv_bfloat16 l0 = __float2bfloat16(acc.x - __bfloat162float(h0));
        __nv_bfloat16 l1 = __float2bfloat16(acc.y - __bfloat162float(h1));
        *(ushort2*)(g_attnH + off) = make_ushort2(__bfloat16_as_ushort(h0),
                                                  __bfloat16_as_ushort(h1));
        *(ushort2*)(g_attnL + off) = make_ushort2(__bfloat16_as_ushort(l0),
                                                  __bfloat16_as_ushort(l1));
    }
}

// ---------------- out-proj on wmma + residual + LayerNorm -------------------
// CTA: 64 rows x 256 cols, K=256 in 8 tiles of 32 (ldm WLDM=40).
// smem: sAh @0 (64*40), sAl, sWh (256*40), sWl  -> 51200 B operands;
// fp32 staging (64 x SLD) aliases everything after the k-loop: 66560 B.
#define SMEM_OP_BYTES (64 * SLD * 4)   // 66560 (> operand 51200)

__global__ __launch_bounds__(256)
void outproj_wmma_kernel(const float* __restrict__ x,
                         const float* __restrict__ gamma,
                         const float* __restrict__ beta,
                         float* __restrict__ out) {
    extern __shared__ __align__(128) unsigned char smo[];
    __nv_bfloat16* sAh = (__nv_bfloat16*)smo;              // 64 x WLDM
    __nv_bfloat16* sAl = sAh + 64 * WLDM;
    __nv_bfloat16* sWh = sAl + 64 * WLDM;                  // 256 x WLDM
    __nv_bfloat16* sWl = sWh + 256 * WLDM;
    float* stage = (float*)smo;                            // 64 x SLD

    int tid = threadIdx.x, wid = tid >> 5, lane = tid & 31;
    int n0 = blockIdx.x * 64;

    const ushort4* AH4 = (const ushort4*)g_attnH;   // row stride 64 ushort4
    const ushort4* AL4 = (const ushort4*)g_attnL;
    const ushort4* WH4 = (const ushort4*)g_WoH;     // row stride 64 ushort4
    const ushort4* WL4 = (const ushort4*)g_WoL;

    int wm = wid & 3;      // 16-row block (4 x 16 = 64 rows)
    int wn = wid >> 2;     // 128-col half
    wmma::fragment<wmma::accumulator, 16, 16, 16, float> acc[8];
    #pragma unroll
    for (int j = 0; j < 8; j++) wmma::fill_fragment(acc[j], 0.0f);

    for (int kt = 0; kt < 8; kt++) {
        __syncthreads();
        {   // attn tile: 64 rows x 32 bf16 = 8 ushort4/row; 4 threads/row x 2 chunks
            int r = tid >> 2, c0 = (tid & 3) * 2;
            #pragma unroll
            for (int c = 0; c < 2; c++) {
                *(ushort4*)(sAh + r * WLDM + (c0 + c) * 4) =
                    AH4[(size_t)(n0 + r) * 64 + kt * 8 + c0 + c];
                *(ushort4*)(sAl + r * WLDM + (c0 + c) * 4) =
                    AL4[(size_t)(n0 + r) * 64 + kt * 8 + c0 + c];
            }
        }
        {   // Wo tile: 256 rows (j) x 32 bf16 = 8 ushort4/row; 1 thread/row x 8
            int r = tid;
            #pragma unroll
            for (int c = 0; c < 8; c++) {
                *(ushort4*)(sWh + r * WLDM + c * 4) = WH4[(size_t)r * 64 + kt * 8 + c];
                *(ushort4*)(sWl + r * WLDM + c * 4) = WL4[(size_t)r * 64 + kt * 8 + c];
            }
        }
        __syncthreads();

        #pragma unroll
        for (int ks = 0; ks < 2; ks++) {
            wmma::fragment<wmma::matrix_a, 16, 16, 16, __nv_bfloat16, wmma::row_major> ah, al;
            wmma::load_matrix_sync(ah, sAh + (wm * 16) * WLDM + ks * 16, WLDM);
            wmma::load_matrix_sync(al, sAl + (wm * 16) * WLDM + ks * 16, WLDM);
            #pragma unroll
            for (int j = 0; j < 8; j++) {
                wmma::fragment<wmma::matrix_b, 16, 16, 16, __nv_bfloat16, wmma::col_major> bhf, blf;
                wmma::load_matrix_sync(bhf, sWh + (wn * 128 + j * 16) * WLDM + ks * 16, WLDM);
                wmma::load_matrix_sync(blf, sWl + (wn * 128 + j * 16) * WLDM + ks * 16, WLDM);
                wmma::mma_sync(acc[j], ah, bhf, acc[j]);
                wmma::mma_sync(acc[j], ah, blf, acc[j]);
                wmma::mma_sync(acc[j], al, bhf, acc[j]);
            }
        }
    }
    __syncthreads();   // done with operand smem; stage aliases it

    #pragma unroll
    for (int j = 0; j < 8; j++)
        wmma::store_matrix_sync(stage + (wm * 16) * SLD + wn * 128 + j * 16,
                                acc[j], SLD, wmma::mem_row_major);
    __syncthreads();

    // residual + LN: warp handles 8 rows, lane covers 8 cols per row
    float gl[8], bl[8];
    #pragma unroll
    for (int i = 0; i < 8; i++) {
        gl[i] = gamma[lane * 8 + i];
        bl[i] = beta[lane * 8 + i];
    }
    for (int rr = 0; rr < 8; rr++) {
        int r = wid * 8 + rr;
        int n = n0 + r;
        float v[8];
        #pragma unroll
        for (int i = 0; i < 8; i += 4) {
            float4 sv = *(float4*)(stage + r * SLD + lane * 8 + i);
            float4 xv = *(const float4*)(x + (size_t)n * DD + lane * 8 + i);
            v[i + 0] = sv.x + xv.x; v[i + 1] = sv.y + xv.y;
            v[i + 2] = sv.z + xv.z; v[i + 3] = sv.w + xv.w;
        }
        float s = 0.f, s2 = 0.f;
        #pragma unroll
        for (int i = 0; i < 8; i++) { s += v[i]; s2 += v[i] * v[i]; }
        #pragma unroll
        for (int o = 16; o; o >>= 1) {
            s  += __shfl_xor_sync(0xffffffffu, s, o);
            s2 += __shfl_xor_sync(0xffffffffu, s2, o);
        }
        float mu = s * (1.0f / DD);
        float rs = rsqrtf(s2 * (1.0f / DD) - mu * mu + EPSV);
        float4 o0, o1;
        o0.x = (v[0] - mu) * rs * gl[0] + bl[0];
        o0.y = (v[1] - mu) * rs * gl[1] + bl[1];
        o0.z = (v[2] - mu) * rs * gl[2] + bl[2];
        o0.w = (v[3] - mu) * rs * gl[3] + bl[3];
        o1.x = (v[4] - mu) * rs * gl[4] + bl[4];
        o1.y = (v[5] - mu) * rs * gl[5] + bl[5];
        o1.z = (v[6] - mu) * rs * gl[6] + bl[6];
        o1.w = (v[7] - mu) * rs * gl[7] + bl[7];
        *(float4*)(out + (size_t)n * DD + lane * 8)     = o0;
        *(float4*)(out + (size_t)n * DD + lane * 8 + 4) = o1;
    }
}

// ---------------- launch ----------------------------------------------------
extern "C" void kernel_launch(void* const* d_in, const int* in_sizes, int n_in,
                              void* d_out, int out_size) {
    const float* x     = (const float*)d_in[0];
    const void*  mask  = d_in[1];
    const float* Wq    = (const float*)d_in[2];
    const float* Wk    = (const float*)d_in[3];
    const float* Wv    = (const float*)d_in[4];
    const float* Wo    = (const float*)d_in[5];
    const float* gamma = (const float*)d_in[6];
    const float* beta  = (const float*)d_in[7];
    float* out = (float*)d_out;

    cudaFuncSetAttribute(score_wmma_kernel,
                         cudaFuncAttributeMaxDynamicSharedMemorySize, SMEM_WMMA_BYTES);
    cudaFuncSetAttribute(qkv_wmma_kernel,
                         cudaFuncAttributeMaxDynamicSharedMemorySize, SMEM_QKV_BYTES);
    cudaFuncSetAttribute(outproj_wmma_kernel,
                         cudaFuncAttributeMaxDynamicSharedMemorySize, SMEM_OP_BYTES);

    mask_prep_kernel<<<1, 256>>>(mask);
    decompose_kernel<<<(NX4 + NW4 + NWO4 + 255) / 256, 256>>>(x, Wq, Wk, Wv, Wo);
    qkv_wmma_kernel<<<dim3(NT / 128, HH, 3), 256, SMEM_QKV_BYTES>>>();
    score_wmma_kernel<<<dim3(16, HH, BB), 256, SMEM_WMMA_BYTES>>>();
    spmax_av_kernel<<<NROWS / 8, 256>>>();
    outproj_wmma_kernel<<<NT / 64, 256, SMEM_OP_BYTES>>>(x, gamma, beta, out);
}

// round 17
// speedup vs baseline: 3.7532x; 1.0339x over previous
#include <cuda_runtime.h>
#include <cuda_bf16.h>
#include <mma.h>
#include <cstdint>

using namespace nvcuda;

#define BB 8
#define TT 2048
#define DD 256
#define HH 4
#define HDIM 64
#define NT (BB*TT)           // 16384 rows
#define NROWS (BB*HH*TT)     // 65536 attention score rows
#define NEGV (-1e9f)
#define EPSV 1e-5f
#define CAND_CAP 512
#define QLDM 72              // bf16 smem leading dim (mult of 8; 144 B row)
#define WLDM 40              // bf16 smem ldm for 32-wide k tiles
#define SLD 260              // fp32 staging ldm in outproj

// ---------------- device scratch (module-load allocated) --------------------
__device__ unsigned short g_Xh[NT*DD];           // bf16 hi of x
__device__ unsigned short g_Xl[NT*DD];           // bf16 lo of x
__device__ unsigned short g_Wh[3*DD*DD];         // bf16 hi of Wq,Wk,Wv
__device__ unsigned short g_Wl[3*DD*DD];         // bf16 lo
__device__ unsigned short g_WoH[DD*DD];          // bf16 hi of Wo
__device__ unsigned short g_WoL[DD*DD];          // bf16 lo of Wo
__device__ unsigned short g_Qh[BB*HH*TT*HDIM];   // bf16 hi of Q/8
__device__ unsigned short g_Ql[BB*HH*TT*HDIM];   // bf16 lo of Q/8
__device__ unsigned short g_Kh[BB*HH*TT*HDIM];   // bf16 hi of K
__device__ unsigned short g_Kl[BB*HH*TT*HDIM];   // bf16 lo of K
__device__ float g_V[BB*HH*TT*HDIM];
__device__ float g_S[(size_t)BB*HH*TT*TT];       // 512 MiB score scratch
__device__ unsigned short g_attnH[NT*DD];        // bf16 hi of attn out
__device__ unsigned short g_attnL[NT*DD];        // bf16 lo
__device__ unsigned char g_pad[NT];

// ---------------- helpers ----------------------------------------------------
__device__ __forceinline__ void split4(float4 v, ushort4& hv, ushort4& lv) {
    __nv_bfloat16 h0 = __float2bfloat16(v.x), h1 = __float2bfloat16(v.y);
    __nv_bfloat16 h2 = __float2bfloat16(v.z), h3 = __float2bfloat16(v.w);
    __nv_bfloat16 l0 = __float2bfloat16(v.x - __bfloat162float(h0));
    __nv_bfloat16 l1 = __float2bfloat16(v.y - __bfloat162float(h1));
    __nv_bfloat16 l2 = __float2bfloat16(v.z - __bfloat162float(h2));
    __nv_bfloat16 l3 = __float2bfloat16(v.w - __bfloat162float(h3));
    hv = make_ushort4(__bfloat16_as_ushort(h0), __bfloat16_as_ushort(h1),
                      __bfloat16_as_ushort(h2), __bfloat16_as_ushort(h3));
    lv = make_ushort4(__bfloat16_as_ushort(l0), __bfloat16_as_ushort(l1),
                      __bfloat16_as_ushort(l2), __bfloat16_as_ushort(l3));
}

__device__ __forceinline__ uint32_t smem_u32(const void* p) {
    uint32_t a;
    asm("{ .reg .u64 t; cvta.to.shared.u64 t, %1; cvt.u32.u64 %0, t; }"
        : "=r"(a) : "l"(p));
    return a;
}
__device__ __forceinline__ void cp_async16(uint32_t dst, const void* src) {
    asm volatile("cp.async.cg.shared.global [%0], [%1], 16;"
                 :: "r"(dst), "l"(src));
}
#define CP_COMMIT() asm volatile("cp.async.commit_group;" ::: "memory")
#define CP_WAIT1()  asm volatile("cp.async.wait_group 1;" ::: "memory")

// ---------------- mask dtype detection + expansion --------------------------
__global__ void mask_prep_kernel(const void* __restrict__ maskraw) {
    __shared__ int cntOff, cnt3F, mode;
    const unsigned char* b = (const unsigned char*)maskraw;
    int tid = threadIdx.x;
    if (tid == 0) { cntOff = 0; cnt3F = 0; }
    __syncthreads();
    int lo = 0, l3 = 0;
    for (int i = tid; i < NT; i += blockDim.x) {
        unsigned char v = b[i];
        if ((i & 3) != 0 && v != 0) lo++;
        if ((i & 3) == 3 && v == 0x3F) l3++;
    }
    atomicAdd(&cntOff, lo);
    atomicAdd(&cnt3F, l3);
    __syncthreads();
    if (tid == 0) {
        if (cnt3F > 0) mode = 2;            // float32
        else if (cntOff > 0) mode = 0;      // uint8 / bool
        else mode = 1;                      // int32
    }
    __syncthreads();
    int m = mode;
    for (int i = tid; i < NT; i += blockDim.x) {
        unsigned char p;
        if (m == 0)      p = (b[i] != 0);
        else if (m == 1) p = (((const int*)maskraw)[i] != 0);
        else             p = (((const float*)maskraw)[i] != 0.0f);
        g_pad[i] = p;
    }
}

// ---------------- decompose x, Wq/Wk/Wv, Wo into bf16 hi/lo ------------------
#define NX4 (NT*DD/4)        // 1048576 float4 of x
#define NW4 (3*DD*DD/4)      // 49152 float4 of Wq/Wk/Wv
#define NWO4 (DD*DD/4)       // 16384 float4 of Wo
__global__ __launch_bounds__(256)
void decompose_kernel(const float* __restrict__ x,
                      const float* __restrict__ Wq,
                      const float* __restrict__ Wk,
                      const float* __restrict__ Wv,
                      const float* __restrict__ Wo) {
    int idx = blockIdx.x * 256 + threadIdx.x;
    if (idx < NX4) {
        float4 v = ((const float4*)x)[idx];
        ushort4 hv, lv;
        split4(v, hv, lv);
        ((ushort4*)g_Xh)[idx] = hv;
        ((ushort4*)g_Xl)[idx] = lv;
    } else if (idx < NX4 + NW4) {
        int w = idx - NX4;
        int z = w / (DD * DD / 4), r = w % (DD * DD / 4);
        const float* W = (z == 0) ? Wq : (z == 1 ? Wk : Wv);
        float4 v = ((const float4*)W)[r];
        ushort4 hv, lv;
        split4(v, hv, lv);
        ((ushort4*)g_Wh)[z * (DD * DD / 4) + r] = hv;
        ((ushort4*)g_Wl)[z * (DD * DD / 4) + r] = lv;
    } else if (idx < NX4 + NW4 + NWO4) {
        int r = idx - NX4 - NW4;
        float4 v = ((const float4*)Wo)[r];
        ushort4 hv, lv;
        split4(v, hv, lv);
        ((ushort4*)g_WoH)[r] = hv;
        ((ushort4*)g_WoL)[r] = lv;
    }
}

// ---------------- QKV projection on wmma (round-14 known-good) ---------------
#define SMEM_QKV_BYTES ((2*128*QLDM + 2*64*QLDM) * 2)   // 55296

__global__ __launch_bounds__(256)
void qkv_wmma_kernel() {
    extern __shared__ __align__(128) unsigned char smq[];
    __nv_bfloat16* sXh = (__nv_bfloat16*)smq;
    __nv_bfloat16* sXl = sXh + 128 * QLDM;
    __nv_bfloat16* sWh = sXl + 128 * QLDM;
    __nv_bfloat16* sWl = sWh + 64 * QLDM;
    float* stage = (float*)smq;               // aliases sXh/sXl after k-loop

    int tid = threadIdx.x, wid = tid >> 5;
    int n0 = blockIdx.x * 128;
    int h  = blockIdx.y;
    int z  = blockIdx.z;
    int j0 = h * 64;

    const ushort4* Xh4 = (const ushort4*)g_Xh;   // row stride 64 ushort4
    const ushort4* Xl4 = (const ushort4*)g_Xl;
    const ushort4* Wh4 = (const ushort4*)g_Wh + (size_t)z * (DD * DD / 4);
    const ushort4* Wl4 = (const ushort4*)g_Wl + (size_t)z * (DD * DD / 4);

    int wm = wid & 3;       // 32-row block
    int wn = wid >> 2;      // 32-col block
    wmma::fragment<wmma::accumulator, 16, 16, 16, float> acc[2][2];
    #pragma unroll
    for (int i = 0; i < 2; i++)
        #pragma unroll
        for (int j = 0; j < 2; j++)
            wmma::fill_fragment(acc[i][j], 0.0f);

    for (int kt = 0; kt < 4; kt++) {
        __syncthreads();
        {   // X tile: 128 rows x 64 bf16 = 16 ushort4/row
            int r = tid >> 1, c0 = (tid & 1) * 8;
            #pragma unroll
            for (int c = 0; c < 8; c++) {
                *(ushort4*)(sXh + r * QLDM + (c0 + c) * 4) =
                    Xh4[(size_t)(n0 + r) * 64 + kt * 16 + c0 + c];
                *(ushort4*)(sXl + r * QLDM + (c0 + c) * 4) =
                    Xl4[(size_t)(n0 + r) * 64 + kt * 16 + c0 + c];
            }
        }
        {   // W tile: 64 rows (j) x 64 bf16; W row stride 64 ushort4
            int r = tid >> 2, c0 = (tid & 3) * 4;
            #pragma unroll
            for (int c = 0; c < 4; c++) {
                *(ushort4*)(sWh + r * QLDM + (c0 + c) * 4) =
                    Wh4[(size_t)(j0 + r) * 64 + kt * 16 + c0 + c];
                *(ushort4*)(sWl + r * QLDM + (c0 + c) * 4) =
                    Wl4[(size_t)(j0 + r) * 64 + kt * 16 + c0 + c];
            }
        }
        __syncthreads();

        #pragma unroll
        for (int ks = 0; ks < 4; ks++) {
            wmma::fragment<wmma::matrix_a, 16, 16, 16, __nv_bfloat16, wmma::row_major> ah[2], al[2];
            #pragma unroll
            for (int i = 0; i < 2; i++) {
                wmma::load_matrix_sync(ah[i], sXh + (wm * 32 + i * 16) * QLDM + ks * 16, QLDM);
                wmma::load_matrix_sync(al[i], sXl + (wm * 32 + i * 16) * QLDM + ks * 16, QLDM);
            }
            #pragma unroll
            for (int j = 0; j < 2; j++) {
                wmma::fragment<wmma::matrix_b, 16, 16, 16, __nv_bfloat16, wmma::col_major> bhf, blf;
                wmma::load_matrix_sync(bhf, sWh + (wn * 32 + j * 16) * QLDM + ks * 16, QLDM);
                wmma::load_matrix_sync(blf, sWl + (wn * 32 + j * 16) * QLDM + ks * 16, QLDM);
                #pragma unroll
                for (int i = 0; i < 2; i++) {
                    wmma::mma_sync(acc[i][j], ah[i], bhf, acc[i][j]);
                    wmma::mma_sync(acc[i][j], ah[i], blf, acc[i][j]);
                    wmma::mma_sync(acc[i][j], al[i], bhf, acc[i][j]);
                }
            }
        }
    }
    __syncthreads();   // done reading sX/sW; staging may alias

    #pragma unroll
    for (int i = 0; i < 2; i++)
        #pragma unroll
        for (int j = 0; j < 2; j++)
            wmma::store_matrix_sync(stage + (wm * 32 + i * 16) * 68 + wn * 32 + j * 16,
                                    acc[i][j], 68, wmma::mem_row_major);
    __syncthreads();

    // epilogue: thread -> row r = tid>>1, cols c0..c0+31
    {
        int r = tid >> 1, c0 = (tid & 1) * 32;
        int n = n0 + r;
        int bi = n >> 11, t = n & (TT - 1);
        size_t off = (((size_t)bi * HH + h) * TT + t) * HDIM + c0;
        float sc = (z == 0) ? 0.125f : 1.0f;
        #pragma unroll
        for (int c = 0; c < 8; c++) {
            float4 v = *(float4*)(stage + r * 68 + c0 + c * 4);
            if (z == 2) {
                *(float4*)(g_V + off + c * 4) = v;
            } else {
                v.x *= sc; v.y *= sc; v.z *= sc; v.w *= sc;
                ushort4 hv, lv;
                split4(v, hv, lv);
                unsigned short* H = (z == 0) ? g_Qh : g_Kh;
                unsigned short* L = (z == 0) ? g_Ql : g_Kl;
                *(ushort4*)(H + off + c * 4) = hv;
                *(ushort4*)(L + off + c * 4) = lv;
            }
        }
    }
}

// ---------------- score GEMM: 512 threads / 16 warps, cp.async K pipeline ---
// Tile 128q x 128k; warp grid 4x4 (wm: 32q block, wn: 32k block).
// smem layout unchanged: sQh @0, sQl @128*QLDM, K buf b hi @(2+2b), lo @(3+2b).
#define SMEM_WMMA_BYTES (6 * 128 * QLDM * 2)

__global__ __launch_bounds__(512)
void score_wmma_kernel() {
    extern __shared__ __align__(128) __nv_bfloat16 sm[];
    __nv_bfloat16* sQh = sm;
    __nv_bfloat16* sQl = sm + 128 * QLDM;
    uint32_t sb32 = smem_u32(sm);

    int tid = threadIdx.x, wid = tid >> 5;
    int qt = blockIdx.x, h = blockIdx.y, b = blockIdx.z;
    size_t bh = (size_t)b * HH + h;

    const ushort4* Qhg = (const ushort4*)(g_Qh + (bh * TT + (size_t)qt * 128) * HDIM);
    const ushort4* Qlg = (const ushort4*)(g_Ql + (bh * TT + (size_t)qt * 128) * HDIM);
    const uint4* Khg4 = (const uint4*)(g_Kh + bh * TT * HDIM);   // row = 8 x uint4
    const uint4* Klg4 = (const uint4*)(g_Kl + bh * TT * HDIM);

    // ---- load Q tile hi/lo: 128 rows x 16 ushort4/row; 4 threads/row ----
    {
        int r = tid >> 2, c0 = (tid & 3) * 4;
        #pragma unroll
        for (int c = 0; c < 4; c++) {
            *(ushort4*)(sQh + r * QLDM + (c0 + c) * 4) = Qhg[r * 16 + c0 + c];
            *(ushort4*)(sQl + r * QLDM + (c0 + c) * 4) = Qlg[r * 16 + c0 + c];
        }
    }

    // ---- async K tile loader: 128 rows x 8 chunks hi + 8 lo; 4 thr/row ----
    int lr = tid >> 2, lc0 = (tid & 3) * 2;       // 2 hi + 2 lo chunks each
    auto loadK = [&](int kt, int bi) {
        const uint4* kh = Khg4 + ((size_t)kt * 128 + lr) * 8 + lc0;
        const uint4* kl = Klg4 + ((size_t)kt * 128 + lr) * 8 + lc0;
        uint32_t dh = sb32 + ((2 + 2 * bi) * 128 * QLDM + lr * QLDM) * 2 + lc0 * 16;
        uint32_t dl = sb32 + ((3 + 2 * bi) * 128 * QLDM + lr * QLDM) * 2 + lc0 * 16;
        #pragma unroll
        for (int c = 0; c < 2; c++) {
            cp_async16(dh + c * 16, kh + c);
            cp_async16(dl + c * 16, kl + c);
        }
    };

    loadK(0, 0); CP_COMMIT();
    loadK(1, 1); CP_COMMIT();

    int wm = wid & 3;      // 32-query block within tile
    int wn = wid >> 2;     // 32-key block within 128-key tile
    float* Sbase = g_S + (bh * TT + (size_t)qt * 128) * TT;

    for (int kt = 0; kt < 16; kt++) {
        int bi = kt & 1;
        __nv_bfloat16* sKh = sm + (2 + 2 * bi) * 128 * QLDM;
        __nv_bfloat16* sKl = sm + (3 + 2 * bi) * 128 * QLDM;
        CP_WAIT1();
        __syncthreads();

        wmma::fragment<wmma::accumulator, 16, 16, 16, float> acc[2][2];
        #pragma unroll
        for (int i = 0; i < 2; i++)
            #pragma unroll
            for (int j = 0; j < 2; j++)
                wmma::fill_fragment(acc[i][j], 0.0f);

        #pragma unroll
        for (int ks = 0; ks < 4; ks++) {
            wmma::fragment<wmma::matrix_a, 16, 16, 16, __nv_bfloat16, wmma::row_major> ah[2], al[2];
            #pragma unroll
            for (int i = 0; i < 2; i++) {
                wmma::load_matrix_sync(ah[i], sQh + (wm * 32 + i * 16) * QLDM + ks * 16, QLDM);
                wmma::load_matrix_sync(al[i], sQl + (wm * 32 + i * 16) * QLDM + ks * 16, QLDM);
            }
            #pragma unroll
            for (int j = 0; j < 2; j++) {
                wmma::fragment<wmma::matrix_b, 16, 16, 16, __nv_bfloat16, wmma::col_major> bhf, blf;
                wmma::load_matrix_sync(bhf, sKh + (wn * 32 + j * 16) * QLDM + ks * 16, QLDM);
                wmma::load_matrix_sync(blf, sKl + (wn * 32 + j * 16) * QLDM + ks * 16, QLDM);
                #pragma unroll
                for (int i = 0; i < 2; i++) {
                    wmma::mma_sync(acc[i][j], ah[i], bhf, acc[i][j]);
                    wmma::mma_sync(acc[i][j], ah[i], blf, acc[i][j]);
                    wmma::mma_sync(acc[i][j], al[i], bhf, acc[i][j]);
                }
            }
        }
        #pragma unroll
        for (int i = 0; i < 2; i++)
            #pragma unroll
            for (int j = 0; j < 2; j++)
                wmma::store_matrix_sync(
                    Sbase + (size_t)(wm * 32 + i * 16) * TT + kt * 128 + wn * 32 + j * 16,
                    acc[i][j], TT, wmma::mem_row_major);

        __syncthreads();
        if (kt + 2 < 16) { loadK(kt + 2, bi); CP_COMMIT(); }
    }
}

// ---------------- sparsemax + sparse AV: emits attn as bf16 hi/lo -----------
__global__ __launch_bounds__(256)
void spmax_av_kernel() {
    __shared__ float sVal[8 * CAND_CAP];           // 16 KB
    __shared__ unsigned short sKey[8 * CAND_CAP];  // 8 KB
    int wid = threadIdx.x >> 5, lane = threadIdx.x & 31;
    int rid = blockIdx.x * 8 + wid;               // [0, NROWS)
    int b = rid >> 13, h = (rid >> 11) & 3, q = rid & 2047;

    const float4* Srow = (const float4*)(g_S + (size_t)rid * TT);
    const uchar4* pad4 = (const uchar4*)(g_pad + b * TT);

    float z[64];
    float zmax = -3e38f;
    #pragma unroll
    for (int it = 0; it < 16; it++) {
        float4 sv = Srow[it * 32 + lane];
        uchar4 p = pad4[it * 32 + lane];
        float z0 = p.x ? NEGV : sv.x;
        float z1 = p.y ? NEGV : sv.y;
        float z2 = p.z ? NEGV : sv.z;
        float z3 = p.w ? NEGV : sv.w;
        z[it * 4 + 0] = z0; z[it * 4 + 1] = z1;
        z[it * 4 + 2] = z2; z[it * 4 + 3] = z3;
        zmax = fmaxf(fmaxf(fmaxf(zmax, z0), fmaxf(z1, z2)), z3);
    }
    #pragma unroll
    for (int o = 16; o; o >>= 1) zmax = fmaxf(zmax, __shfl_xor_sync(0xffffffffu, zmax, o));

    float tau = zmax - 1.0f;
    #pragma unroll 1
    for (int it = 0; it < 5; it++) {
        float s = 0.f, c = 0.f;
        #pragma unroll
        for (int i = 0; i < 64; i++) {
            if (z[i] > tau) { s += z[i]; c += 1.0f; }
        }
        #pragma unroll
        for (int o = 16; o; o >>= 1) {
            s += __shfl_xor_sync(0xffffffffu, s, o);
            c += __shfl_xor_sync(0xffffffffu, c, o);
        }
        float nt = (s - 1.0f) / c;
        if (nt == tau) break;
        tau = nt;
    }

    int base = wid * CAND_CAP;
    unsigned cnt = 0;
    #pragma unroll
    for (int i = 0; i < 64; i++) {
        bool cand = z[i] > tau;
        unsigned m = __ballot_sync(0xffffffffu, cand);
        if (cand) {
            int pos = cnt + __popc(m & ((1u << lane) - 1u));
            if (pos < CAND_CAP) {
                sVal[base + pos] = z[i];
                sKey[base + pos] = (unsigned short)(((i >> 2) << 7) + (lane << 2) + (i & 3));
            }
        }
        cnt += __popc(m);
    }
    __syncwarp();

    const float* Vb = g_V + ((size_t)(b * HH + h) * TT) * HDIM;
    float2 acc = make_float2(0.f, 0.f);

    if (cnt <= CAND_CAP) {
        int n = (int)cnt;
        #pragma unroll 1
        for (int it = 0; it < 27; it++) {
            float s = 0.f, c = 0.f;
            for (int j = lane; j < n; j += 32) {
                float v = sVal[base + j];
                if (v > tau) { s += v; c += 1.0f; }
            }
            #pragma unroll
            for (int o = 16; o; o >>= 1) {
                s += __shfl_xor_sync(0xffffffffu, s, o);
                c += __shfl_xor_sync(0xffffffffu, c, o);
            }
            float nt = (s - 1.0f) / c;
            if (nt == tau) break;
            tau = nt;
        }
        for (int j = 0; j < n; j++) {
            float w = sVal[base + j] - tau;
            if (w > 0.f) {
                int k = sKey[base + j];
                float2 vv = *(const float2*)&Vb[(size_t)k * HDIM + lane * 2];
                acc.x += w * vv.x;
                acc.y += w * vv.y;
            }
        }
    } else {
        #pragma unroll 1
        for (int it = 0; it < 27; it++) {
            float s = 0.f, c = 0.f;
            #pragma unroll
            for (int i = 0; i < 64; i++) {
                if (z[i] > tau) { s += z[i]; c += 1.0f; }
            }
            #pragma unroll
            for (int o = 16; o; o >>= 1) {
                s += __shfl_xor_sync(0xffffffffu, s, o);
                c += __shfl_xor_sync(0xffffffffu, c, o);
            }
            float nt = (s - 1.0f) / c;
            if (nt == tau) break;
            tau = nt;
        }
        #pragma unroll
        for (int g = 0; g < 16; g++) {
            #pragma unroll
            for (int j = 0; j < 4; j++) {
                float zz = z[g * 4 + j];
                unsigned m = __ballot_sync(0xffffffffu, zz > tau);
                while (m) {
                    int src = __ffs(m) - 1;
                    m &= m - 1;
                    float w = __shfl_sync(0xffffffffu, zz, src) - tau;
                    int k = g * 128 + src * 4 + j;
                    float2 v = *(const float2*)&Vb[(size_t)k * HDIM + lane * 2];
                    acc.x += w * v.x;
                    acc.y += w * v.y;
                }
            }
        }
    }
    // emit attn as bf16 hi/lo (fp32 values split; outproj reconstructs)
    {
        size_t off = ((size_t)b * TT + q) * DD + h * HDIM + lane * 2;
        __nv_bfloat16 h0 = __float2bfloat16(acc.x);
        __nv_bfloat16 h1 = __float2bfloat16(acc.y);
        __nv_bfloat16 l0 = __float2bfloat16(acc.x - __bfloat162float(h0));
        __nv_bfloat16 l1 = __float2bfloat16(acc.y - __bfloat162float(h1));
        *(ushort2*)(g_attnH + off) = make_ushort2(__bfloat16_as_ushort(h0),
                                                  __bfloat16_as_ushort(h1));
        *(ushort2*)(g_attnL + off) = make_ushort2(__bfloat16_as_ushort(l0),
                                                  __bfloat16_as_ushort(l1));
    }
}

// ---------------- out-proj on wmma + residual + LayerNorm (round-16 good) ---
#define SMEM_OP_BYTES (64 * SLD * 4)   // 66560

__global__ __launch_bounds__(256)
void outproj_wmma_kernel(const float* __restrict__ x,
                         const float* __restrict__ gamma,
                         const float* __restrict__ beta,
                         float* __restrict__ out) {
    extern __shared__ __align__(128) unsigned char smo[];
    __nv_bfloat16* sAh = (__nv_bfloat16*)smo;              // 64 x WLDM
    __nv_bfloat16* sAl = sAh + 64 * WLDM;
    __nv_bfloat16* sWh = sAl + 64 * WLDM;                  // 256 x WLDM
    __nv_bfloat16* sWl = sWh + 256 * WLDM;
    float* stage = (float*)smo;                            // 64 x SLD

    int tid = threadIdx.x, wid = tid >> 5, lane = tid & 31;
    int n0 = blockIdx.x * 64;

    const ushort4* AH4 = (const ushort4*)g_attnH;   // row stride 64 ushort4
    const ushort4* AL4 = (const ushort4*)g_attnL;
    const ushort4* WH4 = (const ushort4*)g_WoH;     // row stride 64 ushort4
    const ushort4* WL4 = (const ushort4*)g_WoL;

    int wm = wid & 3;      // 16-row block (4 x 16 = 64 rows)
    int wn = wid >> 2;     // 128-col half
    wmma::fragment<wmma::accumulator, 16, 16, 16, float> acc[8];
    #pragma unroll
    for (int j = 0; j < 8; j++) wmma::fill_fragment(acc[j], 0.0f);

    for (int kt = 0; kt < 8; kt++) {
        __syncthreads();
        {   // attn tile: 64 rows x 8 ushort4/row; 4 threads/row x 2 chunks
            int r = tid >> 2, c0 = (tid & 3) * 2;
            #pragma unroll
            for (int c = 0; c < 2; c++) {
                *(ushort4*)(sAh + r * WLDM + (c0 + c) * 4) =
                    AH4[(size_t)(n0 + r) * 64 + kt * 8 + c0 + c];
                *(ushort4*)(sAl + r * WLDM + (c0 + c) * 4) =
                    AL4[(size_t)(n0 + r) * 64 + kt * 8 + c0 + c];
            }
        }
        {   // Wo tile: 256 rows (j) x 8 ushort4/row; 1 thread/row x 8
            int r = tid;
            #pragma unroll
            for (int c = 0; c < 8; c++) {
                *(ushort4*)(sWh + r * WLDM + c * 4) = WH4[(size_t)r * 64 + kt * 8 + c];
                *(ushort4*)(sWl + r * WLDM + c * 4) = WL4[(size_t)r * 64 + kt * 8 + c];
            }
        }
        __syncthreads();

        #pragma unroll
        for (int ks = 0; ks < 2; ks++) {
            wmma::fragment<wmma::matrix_a, 16, 16, 16, __nv_bfloat16, wmma::row_major> ah, al;
            wmma::load_matrix_sync(ah, sAh + (wm * 16) * WLDM + ks * 16, WLDM);
            wmma::load_matrix_sync(al, sAl + (wm * 16) * WLDM + ks * 16, WLDM);
            #pragma unroll
            for (int j = 0; j < 8; j++) {
                wmma::fragment<wmma::matrix_b, 16, 16, 16, __nv_bfloat16, wmma::col_major> bhf, blf;
                wmma::load_matrix_sync(bhf, sWh + (wn * 128 + j * 16) * WLDM + ks * 16, WLDM);
                wmma::load_matrix_sync(blf, sWl + (wn * 128 + j * 16) * WLDM + ks * 16, WLDM);
                wmma::mma_sync(acc[j], ah, bhf, acc[j]);
                wmma::mma_sync(acc[j], ah, blf, acc[j]);
                wmma::mma_sync(acc[j], al, bhf, acc[j]);
            }
        }
    }
    __syncthreads();   // done with operand smem; stage aliases it

    #pragma unroll
    for (int j = 0; j < 8; j++)
        wmma::store_matrix_sync(stage + (wm * 16) * SLD + wn * 128 + j * 16,
                                acc[j], SLD, wmma::mem_row_major);
    __syncthreads();

    // residual + LN: warp handles 8 rows, lane covers 8 cols per row
    float gl[8], bl[8];
    #pragma unroll
    for (int i = 0; i < 8; i++) {
        gl[i] = gamma[lane * 8 + i];
        bl[i] = beta[lane * 8 + i];
    }
    for (int rr = 0; rr < 8; rr++) {
        int r = wid * 8 + rr;
        int n = n0 + r;
        float v[8];
        #pragma unroll
        for (int i = 0; i < 8; i += 4) {
            float4 sv = *(float4*)(stage + r * SLD + lane * 8 + i);
            float4 xv = *(const float4*)(x + (size_t)n * DD + lane * 8 + i);
            v[i + 0] = sv.x + xv.x; v[i + 1] = sv.y + xv.y;
            v[i + 2] = sv.z + xv.z; v[i + 3] = sv.w + xv.w;
        }
        float s = 0.f, s2 = 0.f;
        #pragma unroll
        for (int i = 0; i < 8; i++) { s += v[i]; s2 += v[i] * v[i]; }
        #pragma unroll
        for (int o = 16; o; o >>= 1) {
            s  += __shfl_xor_sync(0xffffffffu, s, o);
            s2 += __shfl_xor_sync(0xffffffffu, s2, o);
        }
        float mu = s * (1.0f / DD);
        float rs = rsqrtf(s2 * (1.0f / DD) - mu * mu + EPSV);
        float4 o0, o1;
        o0.x = (v[0] - mu) * rs * gl[0] + bl[0];
        o0.y = (v[1] - mu) * rs * gl[1] + bl[1];
        o0.z = (v[2] - mu) * rs * gl[2] + bl[2];
        o0.w = (v[3] - mu) * rs * gl[3] + bl[3];
        o1.x = (v[4] - mu) * rs * gl[4] + bl[4];
        o1.y = (v[5] - mu) * rs * gl[5] + bl[5];
        o1.z = (v[6] - mu) * rs * gl[6] + bl[6];
        o1.w = (v[7] - mu) * rs * gl[7] + bl[7];
        *(float4*)(out + (size_t)n * DD + lane * 8)     = o0;
        *(float4*)(out + (size_t)n * DD + lane * 8 + 4) = o1;
    }
}

// ---------------- launch ----------------------------------------------------
extern "C" void kernel_launch(void* const* d_in, const int* in_sizes, int n_in,
                              void* d_out, int out_size) {
    const float* x     = (const float*)d_in[0];
    const void*  mask  = d_in[1];
    const float* Wq    = (const float*)d_in[2];
    const float* Wk    = (const float*)d_in[3];
    const float* Wv    = (const float*)d_in[4];
    const float* Wo    = (const float*)d_in[5];
    const float* gamma = (const float*)d_in[6];
    const float* beta  = (const float*)d_in[7];
    float* out = (float*)d_out;

    cudaFuncSetAttribute(score_wmma_kernel,
                         cudaFuncAttributeMaxDynamicSharedMemorySize, SMEM_WMMA_BYTES);
    cudaFuncSetAttribute(qkv_wmma_kernel,
                         cudaFuncAttributeMaxDynamicSharedMemorySize, SMEM_QKV_BYTES);
    cudaFuncSetAttribute(outproj_wmma_kernel,
                         cudaFuncAttributeMaxDynamicSharedMemorySize, SMEM_OP_BYTES);

    mask_prep_kernel<<<1, 256>>>(mask);
    decompose_kernel<<<(NX4 + NW4 + NWO4 + 255) / 256, 256>>>(x, Wq, Wk, Wv, Wo);
    qkv_wmma_kernel<<<dim3(NT / 128, HH, 3), 256, SMEM_QKV_BYTES>>>();
    score_wmma_kernel<<<dim3(16, HH, BB), 512, SMEM_WMMA_BYTES>>>();
    spmax_av_kernel<<<NROWS / 8, 256>>>();
    outproj_wmma_kernel<<<NT / 64, 256, SMEM_OP_BYTES>>>(x, gamma, beta, out);
}